// round 14
// baseline (speedup 1.0000x reference)
#include <cuda_runtime.h>
#include <cuda_bf16.h>
#include <math.h>
#include <cstdint>

#define S 1024
#define E 1024
#define H 16
#define HD 64
#define BATCH 2
#define BH (BATCH * H)     // 32
#define M_TOT (BATCH * S)  // 2048

// ---------------- scratch (device globals; no runtime allocation) ----------
__device__ __align__(16) float g_logits[BH * S * S];
__device__ __align__(16) float g_rowconst[BH * S];          // MIXED row consts
__device__ __align__(16) float g_suffV[BH * 17 * HD];
__device__ __align__(16) __nv_bfloat16 g_mxh[BH * S * S];   // mixed attn hi
__device__ __align__(16) __nv_bfloat16 g_mxl[BH * S * S];   // mixed attn lo
__device__ __align__(16) __nv_bfloat16 g_ah[3 * M_TOT * E];
__device__ __align__(16) __nv_bfloat16 g_al[3 * M_TOT * E];
__device__ __align__(16) __nv_bfloat16 g_wth[4 * E * E];   // W^T [n][k]
__device__ __align__(16) __nv_bfloat16 g_wtl[4 * E * E];
__device__ __align__(16) __nv_bfloat16 g_aoh[M_TOT * E];
__device__ __align__(16) __nv_bfloat16 g_aol[M_TOT * E];
__device__ __align__(16) __nv_bfloat16 g_pjh[2 * BH * S * HD];  // q,k hi
__device__ __align__(16) __nv_bfloat16 g_pjl[2 * BH * S * HD];  // q,k lo
__device__ __align__(16) __nv_bfloat16 g_vbh[BH * S * HD];      // V hi
__device__ __align__(16) __nv_bfloat16 g_vbl[BH * S * HD];      // V lo

// ============================ PTX helpers ===================================
__device__ __forceinline__ uint32_t smem_u32(const void* p) {
    uint32_t a;
    asm("{ .reg .u64 t; cvta.to.shared.u64 t, %1; cvt.u32.u64 %0, t; }" : "=r"(a) : "l"(p));
    return a;
}
__device__ __forceinline__ void ldsm_x4(uint32_t* r, uint32_t addr) {
    asm volatile("ldmatrix.sync.aligned.m8n8.x4.shared.b16 {%0,%1,%2,%3}, [%4];"
        : "=r"(r[0]), "=r"(r[1]), "=r"(r[2]), "=r"(r[3]) : "r"(addr));
}
__device__ __forceinline__ void ldsm_x4_t(uint32_t* r, uint32_t addr) {
    asm volatile("ldmatrix.sync.aligned.m8n8.x4.trans.shared.b16 {%0,%1,%2,%3}, [%4];"
        : "=r"(r[0]), "=r"(r[1]), "=r"(r[2]), "=r"(r[3]) : "r"(addr));
}
__device__ __forceinline__ void mma_bf16(float* c, const uint32_t* a, const uint32_t* b) {
    asm volatile("mma.sync.aligned.m16n8k16.row.col.f32.bf16.bf16.f32 "
        "{%0,%1,%2,%3}, {%4,%5,%6,%7}, {%8,%9}, {%0,%1,%2,%3};"
        : "+f"(c[0]), "+f"(c[1]), "+f"(c[2]), "+f"(c[3])
        : "r"(a[0]), "r"(a[1]), "r"(a[2]), "r"(a[3]), "r"(b[0]), "r"(b[1]));
}
__device__ __forceinline__ void cp16(uint32_t saddr, const void* g) {
    asm volatile("cp.async.cg.shared.global [%0], [%1], 16;" :: "r"(saddr), "l"(g));
}
__device__ __forceinline__ void cp16ca(uint32_t saddr, const void* g) {
    asm volatile("cp.async.ca.shared.global [%0], [%1], 16;" :: "r"(saddr), "l"(g));
}
// split f32x4 -> one 8B hi store + one 8B lo store (gmem)
__device__ __forceinline__ void split_store4g(__nv_bfloat16* hp, __nv_bfloat16* lp, const float* x) {
    __nv_bfloat16 h0 = __float2bfloat16(x[0]), h1 = __float2bfloat16(x[1]);
    __nv_bfloat16 h2 = __float2bfloat16(x[2]), h3 = __float2bfloat16(x[3]);
    __nv_bfloat162 a = __halves2bfloat162(h0, h1), b = __halves2bfloat162(h2, h3);
    uint2 hv; hv.x = *(uint32_t*)&a; hv.y = *(uint32_t*)&b;
    *(uint2*)hp = hv;
    __nv_bfloat162 c = __halves2bfloat162(
        __float2bfloat16(x[0] - __bfloat162float(h0)),
        __float2bfloat16(x[1] - __bfloat162float(h1)));
    __nv_bfloat162 d = __halves2bfloat162(
        __float2bfloat16(x[2] - __bfloat162float(h2)),
        __float2bfloat16(x[3] - __bfloat162float(h3)));
    uint2 lv; lv.x = *(uint32_t*)&c; lv.y = *(uint32_t*)&d;
    *(uint2*)lp = lv;
}

// GEMM geometry: 128x128 block, BK=32, 8 warps (4m x 2n), warp 32x64.
#define PITCH 40                 // bf16 per smem row (80 B: conflict-free ldmatrix)
#define TILE_B 10240             // 128 * PITCH * 2
#define STAGE_B 40960            // 4 tiles (Ah, Al, Bh, Bl)
#define GEMM_SMEM (2 * STAGE_B)  // 81920

// ============================================================================
// prep (merged): z<3 -> input split (Q,K,V); z>=3 -> weight transpose+split
// ============================================================================
__global__ __launch_bounds__(256) void prep_kernel(
    const float* __restrict__ Q, const float* __restrict__ K, const float* __restrict__ V,
    const float* __restrict__ Wq, const float* __restrict__ Wk,
    const float* __restrict__ Wv, const float* __restrict__ Wo)
{
    int z = blockIdx.z;
    if (z < 3) {
        const float* X = (z == 0) ? Q : (z == 1) ? K : V;
        __nv_bfloat16* hp = g_ah + (size_t)z * M_TOT * E;
        __nv_bfloat16* lp = g_al + (size_t)z * M_TOT * E;
        int i = (blockIdx.x * 256 + threadIdx.x) * 4;
        float4 v = *(const float4*)(X + i);
        float vv[4] = {v.x, v.y, v.z, v.w};
#pragma unroll
        for (int j = 0; j < 4; j++) {
            __nv_bfloat16 h = __float2bfloat16(vv[j]);
            hp[i + j] = h;
            lp[i + j] = __float2bfloat16(vv[j] - __bfloat162float(h));
        }
    } else {
        int bx = blockIdx.x;
        if (bx >= 1024) return;
        int wz = z - 3;
        const float* W = (wz == 0) ? Wq : (wz == 1) ? Wk : (wz == 2) ? Wv : Wo;
        __nv_bfloat16* th = g_wth + (size_t)wz * E * E;
        __nv_bfloat16* tl = g_wtl + (size_t)wz * E * E;
        __shared__ float tile[32][33];
        int n0 = (bx & 31) * 32, k0 = (bx >> 5) * 32;
        int tx = threadIdx.x & 31, ty = threadIdx.x >> 5;
        for (int i = ty; i < 32; i += 8)
            tile[i][tx] = W[(size_t)(k0 + i) * E + n0 + tx];
        __syncthreads();
        for (int i = ty; i < 32; i += 8) {
            float v = tile[tx][i];
            __nv_bfloat16 h = __float2bfloat16(v);
            th[(size_t)(n0 + i) * E + k0 + tx] = h;
            tl[(size_t)(n0 + i) * E + k0 + tx] = __float2bfloat16(v - __bfloat162float(h));
        }
    }
}

// ============================================================================
// mma.sync GEMM core (E-deep, pipelined); weights via .ca (L1-cached)
// ============================================================================
__device__ __forceinline__ void gemm_load_stage(uint32_t sbs,
    const __nv_bfloat16* __restrict__ Ah, const __nv_bfloat16* __restrict__ Al,
    const __nv_bfloat16* __restrict__ Bh, const __nv_bfloat16* __restrict__ Bl,
    int m0, int n0, int k0)
{
    int t = threadIdx.x;
#pragma unroll
    for (int i = 0; i < 2; i++) {
        int idx = t + i * 256;
        int r = idx >> 2, c = (idx & 3) * 8;
        uint32_t so = (uint32_t)(r * PITCH + c) * 2;
        cp16(sbs + so,              Ah + (size_t)(m0 + r) * E + k0 + c);
        cp16(sbs + TILE_B + so,     Al + (size_t)(m0 + r) * E + k0 + c);
        cp16ca(sbs + 2 * TILE_B + so, Bh + (size_t)(n0 + r) * E + k0 + c);
        cp16ca(sbs + 3 * TILE_B + so, Bl + (size_t)(n0 + r) * E + k0 + c);
    }
}

__device__ __forceinline__ void gemm_compute_stage(
    uint32_t sb, int wm, int wn, int a_r, int a_c8, int b_r, int b_c8,
    float cacc[2][8][4])
{
#pragma unroll
    for (int kk = 0; kk < 32; kk += 16) {
        uint32_t ah[2][4], al[2][4], bh[4][4], bl[4][4];
#pragma unroll
        for (int mt = 0; mt < 2; mt++) {
            uint32_t ro = (uint32_t)((wm * 32 + mt * 16 + a_r) * PITCH + kk + a_c8) * 2;
            ldsm_x4(ah[mt], sb + ro);
            ldsm_x4(al[mt], sb + TILE_B + ro);
        }
#pragma unroll
        for (int i = 0; i < 4; i++) {
            uint32_t ro = (uint32_t)((wn * 64 + i * 16 + b_r) * PITCH + kk + b_c8) * 2;
            ldsm_x4(bh[i], sb + 2 * TILE_B + ro);
            ldsm_x4(bl[i], sb + 3 * TILE_B + ro);
        }
#pragma unroll
        for (int mt = 0; mt < 2; mt++)
#pragma unroll
            for (int nt = 0; nt < 8; nt++) {
                const uint32_t* bp  = &bh[nt >> 1][(nt & 1) * 2];
                const uint32_t* blp = &bl[nt >> 1][(nt & 1) * 2];
                mma_bf16(cacc[mt][nt], ah[mt], bp);
                mma_bf16(cacc[mt][nt], al[mt], bp);
                mma_bf16(cacc[mt][nt], ah[mt], blp);
            }
    }
}

__device__ __forceinline__ void gemm_mainloop(uint32_t sb,
    const __nv_bfloat16* Ah, const __nv_bfloat16* Al,
    const __nv_bfloat16* Bh, const __nv_bfloat16* Bl,
    int m0, int n0, int wm, int wn, int a_r, int a_c8, int b_r, int b_c8,
    float cacc[2][8][4])
{
    gemm_load_stage(sb, Ah, Al, Bh, Bl, m0, n0, 0);
    asm volatile("cp.async.commit_group;" ::: "memory");
    for (int c = 0; c < 32; c++) {
        if (c + 1 < 32) {
            gemm_load_stage(sb + ((c + 1) & 1) * STAGE_B, Ah, Al, Bh, Bl, m0, n0, (c + 1) * 32);
            asm volatile("cp.async.commit_group;" ::: "memory");
            asm volatile("cp.async.wait_group 1;" ::: "memory");
        } else {
            asm volatile("cp.async.wait_group 0;" ::: "memory");
        }
        __syncthreads();
        gemm_compute_stage(sb + (c & 1) * STAGE_B, wm, wn, a_r, a_c8, b_r, b_c8, cacc);
        __syncthreads();
    }
}

// ============================================================================
// GEMM kernel A: QKV projections. z<2 -> q/k bf16 splits; z==2 -> V bf16 splits
// ============================================================================
__global__ void __launch_bounds__(256, 2) gemm_qkv_tc(
    const float* __restrict__ bq, const float* __restrict__ bk, const float* __restrict__ bv)
{
    extern __shared__ __align__(16) char smem[];
    uint32_t sb = smem_u32(smem);
    int z = blockIdx.z;
    int m0 = blockIdx.y * 128, n0 = blockIdx.x * 128;
    const __nv_bfloat16* Ah = g_ah + (size_t)z * M_TOT * E;
    const __nv_bfloat16* Al = g_al + (size_t)z * M_TOT * E;
    const __nv_bfloat16* Bh = g_wth + (size_t)z * E * E;
    const __nv_bfloat16* Bl = g_wtl + (size_t)z * E * E;
    const float* bias = (z == 0) ? bq : (z == 1) ? bk : bv;

    int lane = threadIdx.x & 31, wid = threadIdx.x >> 5;
    int wm = wid & 3, wn = wid >> 2;
    int a_r = lane & 15, a_c8 = (lane >> 4) * 8;
    int b_r = (lane & 7) | ((lane >> 4) << 3), b_c8 = ((lane >> 3) & 1) * 8;

    float cacc[2][8][4] = {};
    gemm_mainloop(sb, Ah, Al, Bh, Bl, m0, n0, wm, wn, a_r, a_c8, b_r, b_c8, cacc);

    __nv_bfloat16* ph;
    __nv_bfloat16* pl;
    if (z == 2) { ph = g_vbh; pl = g_vbl; }
    else { ph = g_pjh + (size_t)z * (BH * S * HD); pl = g_pjl + (size_t)z * (BH * S * HD); }

#pragma unroll
    for (int mt = 0; mt < 2; mt++)
#pragma unroll
        for (int nt = 0; nt < 8; nt++) {
            int m = m0 + wm * 32 + mt * 16 + (lane >> 2);
            int n = n0 + wn * 64 + nt * 8 + (lane & 3) * 2;
            int bb = m >> 10, s = m & 1023, h = n >> 6, d = n & 63;
            size_t base = (((size_t)bb * H + h) * S + s) * HD + d;
            float b0 = bias[n], b1 = bias[n + 1];
            float x0 = cacc[mt][nt][0] + b0, x1 = cacc[mt][nt][1] + b1;
            float x2 = cacc[mt][nt][2] + b0, x3 = cacc[mt][nt][3] + b1;
            __nv_bfloat16 h0 = __float2bfloat16(x0), h1 = __float2bfloat16(x1);
            __nv_bfloat16 h2 = __float2bfloat16(x2), h3 = __float2bfloat16(x3);
            *(__nv_bfloat162*)(ph + base) = __halves2bfloat162(h0, h1);
            *(__nv_bfloat162*)(ph + base + 8 * HD) = __halves2bfloat162(h2, h3);
            *(__nv_bfloat162*)(pl + base) = __halves2bfloat162(
                __float2bfloat16(x0 - __bfloat162float(h0)),
                __float2bfloat16(x1 - __bfloat162float(h1)));
            *(__nv_bfloat162*)(pl + base + 8 * HD) = __halves2bfloat162(
                __float2bfloat16(x2 - __bfloat162float(h2)),
                __float2bfloat16(x3 - __bfloat162float(h3)));
        }
}

// ============================================================================
// GEMM kernel B: output projection -> d_out = AO @ Wo + bo
// ============================================================================
__global__ void __launch_bounds__(256, 2) gemm_out_tc(
    const float* __restrict__ bo, float* __restrict__ dout)
{
    extern __shared__ __align__(16) char smem[];
    uint32_t sb = smem_u32(smem);
    int m0 = blockIdx.y * 128, n0 = blockIdx.x * 128;
    const __nv_bfloat16* Bh = g_wth + (size_t)3 * E * E;
    const __nv_bfloat16* Bl = g_wtl + (size_t)3 * E * E;

    int lane = threadIdx.x & 31, wid = threadIdx.x >> 5;
    int wm = wid & 3, wn = wid >> 2;
    int a_r = lane & 15, a_c8 = (lane >> 4) * 8;
    int b_r = (lane & 7) | ((lane >> 4) << 3), b_c8 = ((lane >> 3) & 1) * 8;

    float cacc[2][8][4] = {};
    gemm_mainloop(sb, g_aoh, g_aol, Bh, Bl, m0, n0, wm, wn, a_r, a_c8, b_r, b_c8, cacc);

#pragma unroll
    for (int mt = 0; mt < 2; mt++)
#pragma unroll
        for (int nt = 0; nt < 8; nt++) {
            int m = m0 + wm * 32 + mt * 16 + (lane >> 2);
            int n = n0 + wn * 64 + nt * 8 + (lane & 3) * 2;
            float* op = dout + (size_t)m * E + n;
            float b0 = bo[n], b1 = bo[n + 1];
            *(float2*)op = make_float2(cacc[mt][nt][0] + b0, cacc[mt][nt][1] + b1);
            *(float2*)(op + 8 * E) = make_float2(cacc[mt][nt][2] + b0, cacc[mt][nt][3] + b1);
        }
}

// ============================================================================
// logits via mma (lower-tri tiles)
// ============================================================================
#define LPITCH 72
#define LTILE_B (128 * LPITCH * 2)   // 18432
#define LOG_SMEM (4 * LTILE_B)       // 73728

__global__ void __launch_bounds__(256, 2) logits_mma_kernel()
{
    extern __shared__ __align__(16) char smem[];
    uint32_t sb = smem_u32(smem);
    const int bh = blockIdx.y;
    int t = blockIdx.x, r = 0;
    while (t > r) { t -= r + 1; r++; }
    const int row0 = r * 128;
    const int col0 = t * 128;

    const __nv_bfloat16* Qh = g_pjh + (size_t)bh * S * HD;
    const __nv_bfloat16* Ql = g_pjl + (size_t)bh * S * HD;
    const __nv_bfloat16* Kh = g_pjh + (size_t)(BH + bh) * S * HD;
    const __nv_bfloat16* Kl = g_pjl + (size_t)(BH + bh) * S * HD;
    float* L = g_logits + (size_t)bh * S * S;

    int tid = threadIdx.x, lane = tid & 31, wid = tid >> 5;
    int wm = wid & 3, wn = wid >> 2;
    int a_r = lane & 15, a_c8 = (lane >> 4) * 8;
    int b_r = (lane & 7) | ((lane >> 4) << 3), b_c8 = ((lane >> 3) & 1) * 8;

#pragma unroll
    for (int i = 0; i < 4; i++) {
        int idx = tid + i * 256;
        int rr = idx >> 3, cc = (idx & 7) * 8;
        uint32_t so = (uint32_t)(rr * LPITCH + cc) * 2;
        cp16(sb + so,               Qh + (size_t)(row0 + rr) * HD + cc);
        cp16(sb + LTILE_B + so,     Ql + (size_t)(row0 + rr) * HD + cc);
        cp16(sb + 2 * LTILE_B + so, Kh + (size_t)(col0 + rr) * HD + cc);
        cp16(sb + 3 * LTILE_B + so, Kl + (size_t)(col0 + rr) * HD + cc);
    }
    asm volatile("cp.async.commit_group;" ::: "memory");
    asm volatile("cp.async.wait_group 0;" ::: "memory");
    __syncthreads();

    float cacc[2][8][4] = {};
#pragma unroll
    for (int kk = 0; kk < 64; kk += 16) {
        uint32_t ah[2][4], al[2][4], bhf[4][4], blf[4][4];
#pragma unroll
        for (int mt = 0; mt < 2; mt++) {
            uint32_t ro = (uint32_t)((wm * 32 + mt * 16 + a_r) * LPITCH + kk + a_c8) * 2;
            ldsm_x4(ah[mt], sb + ro);
            ldsm_x4(al[mt], sb + LTILE_B + ro);
        }
#pragma unroll
        for (int i = 0; i < 4; i++) {
            uint32_t ro = (uint32_t)((wn * 64 + i * 16 + b_r) * LPITCH + kk + b_c8) * 2;
            ldsm_x4(bhf[i], sb + 2 * LTILE_B + ro);
            ldsm_x4(blf[i], sb + 3 * LTILE_B + ro);
        }
#pragma unroll
        for (int mt = 0; mt < 2; mt++)
#pragma unroll
            for (int nt = 0; nt < 8; nt++) {
                const uint32_t* bp  = &bhf[nt >> 1][(nt & 1) * 2];
                const uint32_t* blp = &blf[nt >> 1][(nt & 1) * 2];
                mma_bf16(cacc[mt][nt], ah[mt], bp);
                mma_bf16(cacc[mt][nt], al[mt], bp);
                mma_bf16(cacc[mt][nt], ah[mt], blp);
            }
    }

    const float scale = 0.125f;
#pragma unroll
    for (int mt = 0; mt < 2; mt++)
#pragma unroll
        for (int nt = 0; nt < 8; nt++) {
            int m = row0 + wm * 32 + mt * 16 + (lane >> 2);
            int n = col0 + wn * 64 + nt * 8 + (lane & 3) * 2;
            float2 v0, v1;
            v0.x = (n     <= m) ? cacc[mt][nt][0] * scale : 0.f;
            v0.y = (n + 1 <= m) ? cacc[mt][nt][1] * scale : 0.f;
            v1.x = (n     <= m + 8) ? cacc[mt][nt][2] * scale : 0.f;
            v1.y = (n + 1 <= m + 8) ? cacc[mt][nt][3] * scale : 0.f;
            *(float2*)&L[(size_t)m * S + n] = v0;
            *(float2*)&L[(size_t)(m + 8) * S + n] = v1;
        }
}

// ============================================================================
// conv + softmax, HEAD-PAIR per block -> writes MIXED bf16 hi/lo splits
// ============================================================================
__device__ __forceinline__ void conv_load_row2(
    const float* __restrict__ L0, const float* __restrict__ L1, int qp, int c, int tid,
    float* sx0, float* sw0, float* sx1, float* sw1, float r0[6], float r1[6])
{
    float4 v0 = make_float4(0.f, 0.f, 0.f, 0.f);
    float4 v1 = v0;
    if (qp >= 0 && c <= qp) {
        v0 = *(const float4*)&L0[(size_t)qp * S + c];
        v1 = *(const float4*)&L1[(size_t)qp * S + c];
        if (c + 1 > qp) { v0.y = 0.f; v1.y = 0.f; }
        if (c + 2 > qp) { v0.z = 0.f; v1.z = 0.f; }
        if (c + 3 > qp) { v0.w = 0.f; v1.w = 0.f; }
    }
    __syncthreads();               // WAR: previous row's halo + ss reads done
    sx0[tid] = v0.x; sw0[tid] = v0.w;
    sx1[tid] = v1.x; sw1[tid] = v1.w;
    __syncthreads();
    r0[0] = (tid > 0) ? sw0[tid - 1] : 0.f;
    r0[1] = v0.x; r0[2] = v0.y; r0[3] = v0.z; r0[4] = v0.w;
    r0[5] = (tid < 255) ? sx0[tid + 1] : 0.f;
    r1[0] = (tid > 0) ? sw1[tid - 1] : 0.f;
    r1[1] = v1.x; r1[2] = v1.y; r1[3] = v1.z; r1[4] = v1.w;
    r1[5] = (tid < 255) ? sx1[tid + 1] : 0.f;
}

#define QROWS 8
__global__ __launch_bounds__(256) void conv_softmax_kernel(
    const float* __restrict__ kq_w, const float* __restrict__ kq_b,
    const float* __restrict__ mix_w)
{
    const int pb = blockIdx.y;               // pair index 0..15
    const int b = pb >> 3, hp = pb & 7;
    const int h0 = hp * 2, h1 = h0 + 1;
    const int bh0 = b * 16 + h0, bh1 = bh0 + 1;
    const int q0 = blockIdx.x * QROWS;
    const float* L0 = g_logits + (size_t)bh0 * S * S;
    const float* L1 = g_logits + (size_t)bh1 * S * S;

    __shared__ float sx0[256], sw0[256], sx1[256], sw1[256], ss0[8], ss1[8];
    const int tid = threadIdx.x;
    const int lane = tid & 31, wrp = tid >> 5;
    const int c = tid * 4;

    float wv0[9], wv1[9];
#pragma unroll
    for (int t = 0; t < 9; t++) { wv0[t] = kq_w[h0 * 9 + t]; wv1[t] = kq_w[h1 * 9 + t]; }
    const float bias0 = kq_b[h0], bias1 = kq_b[h1];
    const float eb0 = __expf(bias0), eb1 = __expf(bias1);
    const float m00 = mix_w[h0 * 2 + 0], m01 = mix_w[h0 * 2 + 1];
    const float m10 = mix_w[h1 * 2 + 0], m11 = mix_w[h1 * 2 + 1];

    float ra0[6], rb0[6], rc0[6], ra1[6], rb1[6], rc1[6];
    conv_load_row2(L0, L1, q0 - 2, c, tid, sx0, sw0, sx1, sw1, ra0, ra1);
    conv_load_row2(L0, L1, q0 - 1, c, tid, sx0, sw0, sx1, sw1, rb0, rb1);

    for (int i = 0; i < QROWS; i++) {
        const int q = q0 + i;
        conv_load_row2(L0, L1, q, c, tid, sx0, sw0, sx1, sw1, rc0, rc1);
        const int kmax = (q + 1 < S - 1) ? (q + 1) : (S - 1);

        float e0[4], e1[4];
        float es0 = 0.f, es1 = 0.f;
#pragma unroll
        for (int u = 0; u < 4; u++) {
            if (c + u <= kmax) {
                float c0 = wv0[0] * ra0[u] + wv0[1] * ra0[u + 1] + wv0[2] * ra0[u + 2]
                         + wv0[3] * rb0[u] + wv0[4] * rb0[u + 1] + wv0[5] * rb0[u + 2]
                         + wv0[6] * rc0[u] + wv0[7] * rc0[u + 1] + wv0[8] * rc0[u + 2] + bias0;
                float c1 = wv1[0] * ra1[u] + wv1[1] * ra1[u + 1] + wv1[2] * ra1[u + 2]
                         + wv1[3] * rb1[u] + wv1[4] * rb1[u + 1] + wv1[5] * rb1[u + 2]
                         + wv1[6] * rc1[u] + wv1[7] * rc1[u + 1] + wv1[8] * rc1[u + 2] + bias1;
                e0[u] = __expf(c0); es0 += e0[u];
                e1[u] = __expf(c1); es1 += e1[u];
            } else { e0[u] = 0.f; e1[u] = 0.f; }
        }
        float s0 = es0, s1 = es1;
#pragma unroll
        for (int o = 16; o; o >>= 1) {
            s0 += __shfl_xor_sync(0xffffffffu, s0, o);
            s1 += __shfl_xor_sync(0xffffffffu, s1, o);
        }
        if (lane == 0) { ss0[wrp] = s0; ss1[wrp] = s1; }
        __syncthreads();
        float t0 = ss0[lane & 7], t1 = ss1[lane & 7];
#pragma unroll
        for (int o = 4; o; o >>= 1) {
            t0 += __shfl_xor_sync(0xffffffffu, t0, o);
            t1 += __shfl_xor_sync(0xffffffffu, t1, o);
        }

        int cnt = S - 2 - q; if (cnt < 0) cnt = 0;
        float inv0 = 1.f / (t0 + (float)cnt * eb0);
        float inv1 = 1.f / (t1 + (float)cnt * eb1);
        float c0v = eb0 * inv0, c1v = eb1 * inv1;
        float cm0 = m00 * c0v + m01 * c1v;   // mixed const for output head h0
        float cm1 = m10 * c0v + m11 * c1v;   // mixed const for output head h1
        if (tid == 0) {
            g_rowconst[bh0 * S + q] = cm0;
            g_rowconst[bh1 * S + q] = cm1;
        }

        int Klim = ((q >> 6) << 6) + 128; if (Klim > S) Klim = S;
        if (c < Klim) {
            float a0[4], a1[4], x0[4], x1[4];
#pragma unroll
            for (int u = 0; u < 4; u++) {
                a0[u] = (c + u <= kmax) ? e0[u] * inv0 : c0v;
                a1[u] = (c + u <= kmax) ? e1[u] * inv1 : c1v;
                x0[u] = m00 * a0[u] + m01 * a1[u];
                x1[u] = m10 * a0[u] + m11 * a1[u];
            }
            size_t off0 = (size_t)bh0 * S * S + (size_t)q * S + c;
            size_t off1 = (size_t)bh1 * S * S + (size_t)q * S + c;
            split_store4g(g_mxh + off0, g_mxl + off0, x0);
            split_store4g(g_mxh + off1, g_mxl + off1, x1);
        }

#pragma unroll
        for (int u = 0; u < 6; u++) {
            ra0[u] = rb0[u]; rb0[u] = rc0[u];
            ra1[u] = rb1[u]; rb1[u] = rc1[u];
        }
    }
}

// ============================================================================
// V chunk sums (from bf16 hi/lo) + suffix scan
// ============================================================================
__global__ __launch_bounds__(256) void vchunk_kernel()
{
    const int bh = blockIdx.x, ci = blockIdx.y;
    const int tid = threadIdx.x;
    const int d = tid & 63, rg = tid >> 6;
    const __nv_bfloat16* Vh = g_vbh + (size_t)bh * S * HD;
    const __nv_bfloat16* Vl = g_vbl + (size_t)bh * S * HD;
    float s = 0.f;
#pragma unroll
    for (int r = 0; r < 16; r++) {
        size_t o = (size_t)(ci * 64 + rg * 16 + r) * HD + d;
        s += __bfloat162float(Vh[o]) + __bfloat162float(Vl[o]);
    }
    __shared__ float sm[4][64];
    sm[rg][d] = s;
    __syncthreads();
    if (tid < 64)
        g_suffV[((size_t)bh * 17 + ci) * HD + tid] = sm[0][tid] + sm[1][tid] + sm[2][tid] + sm[3][tid];
}

__global__ void vscan_kernel()
{
    const int bh = blockIdx.x, d = threadIdx.x;
    g_suffV[((size_t)bh * 17 + 16) * HD + d] = 0.f;
    float suf = 0.f;
    for (int ci = 15; ci >= 0; ci--) {
        suf += g_suffV[((size_t)bh * 17 + ci) * HD + d];
        g_suffV[((size_t)bh * 17 + ci) * HD + d] = suf;
    }
}

// ============================================================================
// pv via mma: A = pre-mixed bf16 splits (cp.async), B = V splits (trans ldsm)
// ============================================================================
#define PV_APITCH 40
#define PV_VPITCH 136
#define PV_ATILE (64 * PV_APITCH * 2)          // 5120
#define PV_VTILE (32 * PV_VPITCH * 2)          // 8704
#define PV_STAGE (4 * PV_ATILE + 2 * PV_VTILE) // 37888
#define PV_SMEM (2 * PV_STAGE)                 // 75776

__device__ __forceinline__ void pv_load_stage(uint32_t sb, int stage,
    const __nv_bfloat16* __restrict__ A0h, const __nv_bfloat16* __restrict__ A0l,
    const __nv_bfloat16* __restrict__ A1h, const __nv_bfloat16* __restrict__ A1l,
    const __nv_bfloat16* __restrict__ V0h, const __nv_bfloat16* __restrict__ V0l,
    const __nv_bfloat16* __restrict__ V1h, const __nv_bfloat16* __restrict__ V1l,
    int k0)
{
    const int tid = threadIdx.x;
    uint32_t base = sb + stage * PV_STAGE;
    {
        int r = tid >> 2, ch = tid & 3;
        uint32_t so = (uint32_t)(r * PV_APITCH * 2 + ch * 16);
        size_t go = (size_t)r * S + k0 + ch * 8;
        cp16(base + so,                A0h + go);
        cp16(base + PV_ATILE + so,     A0l + go);
        cp16(base + 2 * PV_ATILE + so, A1h + go);
        cp16(base + 3 * PV_ATILE + so, A1l + go);
    }
    uint32_t vbase = base + 4 * PV_ATILE;
#pragma unroll
    for (int i = 0; i < 2; i++) {
        int idx = tid + i * 256;
        int r = idx >> 4, ch = idx & 15;
        uint32_t so = (uint32_t)(r * PV_VPITCH * 2 + ch * 16);
        size_t go = (size_t)(k0 + r) * HD;
        if (ch < 8) {
            cp16(vbase + so,            V0h + go + ch * 8);
            cp16(vbase + PV_VTILE + so, V0l + go + ch * 8);
        } else {
            cp16(vbase + so,            V1h + go + (ch - 8) * 8);
            cp16(vbase + PV_VTILE + so, V1l + go + (ch - 8) * 8);
        }
    }
}

__global__ void __launch_bounds__(256, 2) pv_mma_kernel(
    const float* __restrict__ mix_b,
    const float* __restrict__ dyt_alpha, const float* __restrict__ dyt_w,
    const float* __restrict__ dyt_b, const float* __restrict__ depth_scale)
{
    extern __shared__ __align__(16) char smem[];
    uint32_t sb = smem_u32(smem);
    const int pair = blockIdx.z;
    const int b = pair >> 3, hp = pair & 7;
    const int h0 = hp * 2, h1 = h0 + 1;
    const int bh0 = b * 16 + h0, bh1 = bh0 + 1;
    const int Q0 = (gridDim.y - 1 - blockIdx.y) * 64;
    int Klim = Q0 + 128; if (Klim > S) Klim = S;
    const int cidx = Klim >> 6;
    const int nch = Klim >> 5;

    const __nv_bfloat16* A0h = g_mxh + (size_t)bh0 * S * S + (size_t)Q0 * S;
    const __nv_bfloat16* A0l = g_mxl + (size_t)bh0 * S * S + (size_t)Q0 * S;
    const __nv_bfloat16* A1h = g_mxh + (size_t)bh1 * S * S + (size_t)Q0 * S;
    const __nv_bfloat16* A1l = g_mxl + (size_t)bh1 * S * S + (size_t)Q0 * S;
    const __nv_bfloat16* V0h = g_vbh + (size_t)bh0 * S * HD;
    const __nv_bfloat16* V0l = g_vbl + (size_t)bh0 * S * HD;
    const __nv_bfloat16* V1h = g_vbh + (size_t)bh1 * S * HD;
    const __nv_bfloat16* V1l = g_vbl + (size_t)bh1 * S * HD;

    const int tid = threadIdx.x, lane = tid & 31, wid = tid >> 5;
    const int wm = wid & 3, wn = wid >> 2;
    const int a_r = lane & 15, a_c8 = (lane >> 4) * 8;
    const int bt_r = lane & 15, bt_c8 = (lane >> 4) * 8;

    float acc[8][4] = {};

    pv_load_stage(sb, 0, A0h, A0l, A1h, A1l, V0h, V0l, V1h, V1l, 0);
    asm volatile("cp.async.commit_group;" ::: "memory");

    for (int c = 0; c < nch; c++) {
        if (c + 1 < nch) {
            pv_load_stage(sb, (c + 1) & 1, A0h, A0l, A1h, A1l, V0h, V0l, V1h, V1l, (c + 1) * 32);
            asm volatile("cp.async.commit_group;" ::: "memory");
            asm volatile("cp.async.wait_group 1;" ::: "memory");
        } else {
            asm volatile("cp.async.wait_group 0;" ::: "memory");
        }
        __syncthreads();
        uint32_t base = sb + (c & 1) * PV_STAGE;
        uint32_t sAh = base + (wn * 2) * PV_ATILE;
        uint32_t sAl = base + (wn * 2 + 1) * PV_ATILE;
        uint32_t sVh = base + 4 * PV_ATILE;
        uint32_t sVl = sVh + PV_VTILE;
#pragma unroll
        for (int kk = 0; kk < 32; kk += 16) {
            uint32_t ah[4], al[4];
            uint32_t ro = (uint32_t)((wm * 16 + a_r) * PV_APITCH + kk + a_c8) * 2;
            ldsm_x4(ah, sAh + ro);
            ldsm_x4(al, sAl + ro);
            uint32_t bhf[4][4], blf[4][4];
#pragma unroll
            for (int t = 0; t < 4; t++) {
                uint32_t vo = (uint32_t)((kk + bt_r) * PV_VPITCH + wn * 64 + t * 16 + bt_c8) * 2;
                ldsm_x4_t(bhf[t], sVh + vo);
                ldsm_x4_t(blf[t], sVl + vo);
            }
#pragma unroll
            for (int nt = 0; nt < 8; nt++) {
                const uint32_t* bp  = &bhf[nt >> 1][(nt & 1) * 2];
                const uint32_t* blp = &blf[nt >> 1][(nt & 1) * 2];
                mma_bf16(acc[nt], ah, bp);
                mma_bf16(acc[nt], al, bp);
                mma_bf16(acc[nt], ah, blp);
            }
        }
        __syncthreads();
    }

    const int bhh = wn ? bh1 : bh0;
    const float* suff = g_suffV + ((size_t)bhh * 17 + cidx) * HD;
    const float* csum = g_suffV + ((size_t)bhh * 17 + 0) * HD;
    const float* rcm = g_rowconst + bhh * S;
    const float mb = mix_b[wn ? h1 : h0];
    const float alpha = dyt_alpha[0], ds = depth_scale[0];
    const int q0r = Q0 + wm * 16 + (lane >> 2);
    const float cm0 = rcm[q0r];
    const float cm1 = rcm[q0r + 8];
    __nv_bfloat16* Oh = g_aoh + (size_t)b * S * E + h0 * HD;
    __nv_bfloat16* Ol = g_aol + (size_t)b * S * E + h0 * HD;

#pragma unroll
    for (int nt = 0; nt < 8; nt++) {
        int d = wn * 64 + nt * 8 + (lane & 3) * 2;
        int dl = d & 63;
        float sw0 = suff[dl], sw1 = suff[dl + 1];
        float cs0 = csum[dl], cs1 = csum[dl + 1];
        float w0 = dyt_w[dl], w1 = dyt_w[dl + 1];
        float bb0 = dyt_b[dl], bb1 = dyt_b[dl + 1];
#pragma unroll
        for (int half = 0; half < 2; half++) {
            int q = q0r + half * 8;
            float cm = half ? cm1 : cm0;
            float v0 = acc[nt][half * 2 + 0] + cm * sw0 + mb * cs0;
            float v1 = acc[nt][half * 2 + 1] + cm * sw1 + mb * cs1;
            v0 = (tanhf(alpha * v0) * w0 + bb0) * ds;
            v1 = (tanhf(alpha * v1) * w1 + bb1) * ds;
            __nv_bfloat16 h0v = __float2bfloat16(v0), h1v = __float2bfloat16(v1);
            *(__nv_bfloat162*)&Oh[(size_t)q * E + d] = __halves2bfloat162(h0v, h1v);
            *(__nv_bfloat162*)&Ol[(size_t)q * E + d] = __halves2bfloat162(
                __float2bfloat16(v0 - __bfloat162float(h0v)),
                __float2bfloat16(v1 - __bfloat162float(h1v)));
        }
    }
}

// ============================================================================
// Launch
// ============================================================================
extern "C" void kernel_launch(void* const* d_in, const int* in_sizes, int n_in,
                              void* d_out, int out_size)
{
    const float* Q   = (const float*)d_in[0];
    const float* K   = (const float*)d_in[1];
    const float* V   = (const float*)d_in[2];
    const float* Wq  = (const float*)d_in[3];
    const float* bq  = (const float*)d_in[4];
    const float* Wk  = (const float*)d_in[5];
    const float* bk  = (const float*)d_in[6];
    const float* Wv  = (const float*)d_in[7];
    const float* bv  = (const float*)d_in[8];
    const float* Wo  = (const float*)d_in[9];
    const float* bo  = (const float*)d_in[10];
    const float* kq_w = (const float*)d_in[11];
    const float* kq_b = (const float*)d_in[12];
    const float* mix_w = (const float*)d_in[13];
    const float* mix_b = (const float*)d_in[14];
    const float* dyt_alpha = (const float*)d_in[15];
    const float* dyt_w = (const float*)d_in[16];
    const float* dyt_b = (const float*)d_in[17];
    const float* depth_scale = (const float*)d_in[18];

    cudaFuncSetAttribute(gemm_qkv_tc, cudaFuncAttributeMaxDynamicSharedMemorySize, GEMM_SMEM);
    cudaFuncSetAttribute(gemm_out_tc, cudaFuncAttributeMaxDynamicSharedMemorySize, GEMM_SMEM);
    cudaFuncSetAttribute(logits_mma_kernel, cudaFuncAttributeMaxDynamicSharedMemorySize, LOG_SMEM);
    cudaFuncSetAttribute(pv_mma_kernel, cudaFuncAttributeMaxDynamicSharedMemorySize, PV_SMEM);

    prep_kernel<<<dim3(2048, 1, 7), 256>>>(Q, K, V, Wq, Wk, Wv, Wo);
    gemm_qkv_tc<<<dim3(8, 16, 3), 256, GEMM_SMEM>>>(bq, bk, bv);
    vchunk_kernel<<<dim3(BH, 16), 256>>>();
    vscan_kernel<<<BH, 64>>>();
    logits_mma_kernel<<<dim3(36, BH), 256, LOG_SMEM>>>();
    conv_softmax_kernel<<<dim3(S / QROWS, BH / 2), 256>>>(kq_w, kq_b, mix_w);
    pv_mma_kernel<<<dim3(1, S / 64, BH / 2), 256, PV_SMEM>>>(mix_b, dyt_alpha, dyt_w, dyt_b, depth_scale);
    gemm_out_tc<<<dim3(8, 16), 256, GEMM_SMEM>>>(bo, (float*)d_out);
}

// round 15
// speedup vs baseline: 1.5199x; 1.5199x over previous
#include <cuda_runtime.h>
#include <cuda_bf16.h>
#include <math.h>
#include <cstdint>

#define S 1024
#define E 1024
#define H 16
#define HD 64
#define BATCH 2
#define BH (BATCH * H)     // 32
#define M_TOT (BATCH * S)  // 2048

// ---------------- scratch (device globals; no runtime allocation) ----------
__device__ __align__(16) float g_logits[BH * S * S];
__device__ __align__(16) float g_rowconst[BH * S];          // MIXED row consts
__device__ __align__(16) float g_suffV[BH * 17 * HD];
__device__ __align__(16) float g_chunkV[BH * 16 * HD];
__device__ __align__(16) __nv_bfloat16 g_mxh[BH * S * S];   // mixed attn hi
__device__ __align__(16) __nv_bfloat16 g_mxl[BH * S * S];   // mixed attn lo
__device__ __align__(16) __nv_bfloat16 g_ah[3 * M_TOT * E];
__device__ __align__(16) __nv_bfloat16 g_al[3 * M_TOT * E];
__device__ __align__(16) __nv_bfloat16 g_wth[4 * E * E];   // W^T [n][k]
__device__ __align__(16) __nv_bfloat16 g_wtl[4 * E * E];
__device__ __align__(16) __nv_bfloat16 g_aoh[M_TOT * E];
__device__ __align__(16) __nv_bfloat16 g_aol[M_TOT * E];
__device__ __align__(16) __nv_bfloat16 g_pjh[2 * BH * S * HD];  // q,k hi
__device__ __align__(16) __nv_bfloat16 g_pjl[2 * BH * S * HD];  // q,k lo
__device__ __align__(16) __nv_bfloat16 g_vbh[BH * S * HD];      // V hi
__device__ __align__(16) __nv_bfloat16 g_vbl[BH * S * HD];      // V lo

// ============================ PTX helpers ===================================
__device__ __forceinline__ uint32_t smem_u32(const void* p) {
    uint32_t a;
    asm("{ .reg .u64 t; cvta.to.shared.u64 t, %1; cvt.u32.u64 %0, t; }" : "=r"(a) : "l"(p));
    return a;
}
__device__ __forceinline__ void ldsm_x4(uint32_t* r, uint32_t addr) {
    asm volatile("ldmatrix.sync.aligned.m8n8.x4.shared.b16 {%0,%1,%2,%3}, [%4];"
        : "=r"(r[0]), "=r"(r[1]), "=r"(r[2]), "=r"(r[3]) : "r"(addr));
}
__device__ __forceinline__ void ldsm_x4_t(uint32_t* r, uint32_t addr) {
    asm volatile("ldmatrix.sync.aligned.m8n8.x4.trans.shared.b16 {%0,%1,%2,%3}, [%4];"
        : "=r"(r[0]), "=r"(r[1]), "=r"(r[2]), "=r"(r[3]) : "r"(addr));
}
__device__ __forceinline__ void mma_bf16(float* c, const uint32_t* a, const uint32_t* b) {
    asm volatile("mma.sync.aligned.m16n8k16.row.col.f32.bf16.bf16.f32 "
        "{%0,%1,%2,%3}, {%4,%5,%6,%7}, {%8,%9}, {%0,%1,%2,%3};"
        : "+f"(c[0]), "+f"(c[1]), "+f"(c[2]), "+f"(c[3])
        : "r"(a[0]), "r"(a[1]), "r"(a[2]), "r"(a[3]), "r"(b[0]), "r"(b[1]));
}
__device__ __forceinline__ void cp16(uint32_t saddr, const void* g) {
    asm volatile("cp.async.cg.shared.global [%0], [%1], 16;" :: "r"(saddr), "l"(g));
}
__device__ __forceinline__ void cp16ca(uint32_t saddr, const void* g) {
    asm volatile("cp.async.ca.shared.global [%0], [%1], 16;" :: "r"(saddr), "l"(g));
}
// split f32x4 -> one 8B hi store + one 8B lo store (gmem)
__device__ __forceinline__ void split_store4g(__nv_bfloat16* hp, __nv_bfloat16* lp, const float* x) {
    __nv_bfloat16 h0 = __float2bfloat16(x[0]), h1 = __float2bfloat16(x[1]);
    __nv_bfloat16 h2 = __float2bfloat16(x[2]), h3 = __float2bfloat16(x[3]);
    __nv_bfloat162 a = __halves2bfloat162(h0, h1), b = __halves2bfloat162(h2, h3);
    uint2 hv; hv.x = *(uint32_t*)&a; hv.y = *(uint32_t*)&b;
    *(uint2*)hp = hv;
    __nv_bfloat162 c = __halves2bfloat162(
        __float2bfloat16(x[0] - __bfloat162float(h0)),
        __float2bfloat16(x[1] - __bfloat162float(h1)));
    __nv_bfloat162 d = __halves2bfloat162(
        __float2bfloat16(x[2] - __bfloat162float(h2)),
        __float2bfloat16(x[3] - __bfloat162float(h3)));
    uint2 lv; lv.x = *(uint32_t*)&c; lv.y = *(uint32_t*)&d;
    *(uint2*)lp = lv;
}

// GEMM geometry: 128x128 block, BK=32, 8 warps (4m x 2n), warp 32x64.
#define PITCH 40                 // bf16 per smem row (80 B: conflict-free ldmatrix)
#define TILE_B 10240             // 128 * PITCH * 2
#define STAGE_B 40960            // 4 tiles (Ah, Al, Bh, Bl)
#define GEMM_SMEM (2 * STAGE_B)  // 81920

// ============================================================================
// prep: split f32 -> bf16 hi/lo (Q, K, V inputs)
// ============================================================================
__global__ __launch_bounds__(256) void asplit_kernel(
    const float* __restrict__ Q, const float* __restrict__ K, const float* __restrict__ V)
{
    int z = blockIdx.z;
    const float* X = (z == 0) ? Q : (z == 1) ? K : V;
    __nv_bfloat16* hp = g_ah + (size_t)z * M_TOT * E;
    __nv_bfloat16* lp = g_al + (size_t)z * M_TOT * E;
    int i = (blockIdx.x * 256 + threadIdx.x) * 4;
    float4 v = *(const float4*)(X + i);
    float vv[4] = {v.x, v.y, v.z, v.w};
#pragma unroll
    for (int j = 0; j < 4; j++) {
        __nv_bfloat16 h = __float2bfloat16(vv[j]);
        hp[i + j] = h;
        lp[i + j] = __float2bfloat16(vv[j] - __bfloat162float(h));
    }
}

// ============================================================================
// prep: transpose + split weights: Wt[n][k] = W[k][n], bf16 hi/lo
// ============================================================================
__global__ void wsplit_kernel(const float* __restrict__ Wq, const float* __restrict__ Wk,
                              const float* __restrict__ Wv, const float* __restrict__ Wo)
{
    int z = blockIdx.z;
    const float* W = (z == 0) ? Wq : (z == 1) ? Wk : (z == 2) ? Wv : Wo;
    __nv_bfloat16* th = g_wth + (size_t)z * E * E;
    __nv_bfloat16* tl = g_wtl + (size_t)z * E * E;
    __shared__ float tile[32][33];
    int n0 = blockIdx.x * 32, k0 = blockIdx.y * 32;
    int tx = threadIdx.x, ty = threadIdx.y;
    for (int i = ty; i < 32; i += 8)
        tile[i][tx] = W[(size_t)(k0 + i) * E + n0 + tx];
    __syncthreads();
    for (int i = ty; i < 32; i += 8) {
        float v = tile[tx][i];
        __nv_bfloat16 h = __float2bfloat16(v);
        th[(size_t)(n0 + i) * E + k0 + tx] = h;
        tl[(size_t)(n0 + i) * E + k0 + tx] = __float2bfloat16(v - __bfloat162float(h));
    }
}

// ============================================================================
// mma.sync GEMM core (E-deep, pipelined); weights via .ca (L1-cached)
// ============================================================================
__device__ __forceinline__ void gemm_load_stage(uint32_t sbs,
    const __nv_bfloat16* __restrict__ Ah, const __nv_bfloat16* __restrict__ Al,
    const __nv_bfloat16* __restrict__ Bh, const __nv_bfloat16* __restrict__ Bl,
    int m0, int n0, int k0)
{
    int t = threadIdx.x;
#pragma unroll
    for (int i = 0; i < 2; i++) {
        int idx = t + i * 256;
        int r = idx >> 2, c = (idx & 3) * 8;
        uint32_t so = (uint32_t)(r * PITCH + c) * 2;
        cp16(sbs + so,              Ah + (size_t)(m0 + r) * E + k0 + c);
        cp16(sbs + TILE_B + so,     Al + (size_t)(m0 + r) * E + k0 + c);
        cp16ca(sbs + 2 * TILE_B + so, Bh + (size_t)(n0 + r) * E + k0 + c);
        cp16ca(sbs + 3 * TILE_B + so, Bl + (size_t)(n0 + r) * E + k0 + c);
    }
}

__device__ __forceinline__ void gemm_compute_stage(
    uint32_t sb, int wm, int wn, int a_r, int a_c8, int b_r, int b_c8,
    float cacc[2][8][4])
{
#pragma unroll
    for (int kk = 0; kk < 32; kk += 16) {
        uint32_t ah[2][4], al[2][4], bh[4][4], bl[4][4];
#pragma unroll
        for (int mt = 0; mt < 2; mt++) {
            uint32_t ro = (uint32_t)((wm * 32 + mt * 16 + a_r) * PITCH + kk + a_c8) * 2;
            ldsm_x4(ah[mt], sb + ro);
            ldsm_x4(al[mt], sb + TILE_B + ro);
        }
#pragma unroll
        for (int i = 0; i < 4; i++) {
            uint32_t ro = (uint32_t)((wn * 64 + i * 16 + b_r) * PITCH + kk + b_c8) * 2;
            ldsm_x4(bh[i], sb + 2 * TILE_B + ro);
            ldsm_x4(bl[i], sb + 3 * TILE_B + ro);
        }
#pragma unroll
        for (int mt = 0; mt < 2; mt++)
#pragma unroll
            for (int nt = 0; nt < 8; nt++) {
                const uint32_t* bp  = &bh[nt >> 1][(nt & 1) * 2];
                const uint32_t* blp = &bl[nt >> 1][(nt & 1) * 2];
                mma_bf16(cacc[mt][nt], ah[mt], bp);
                mma_bf16(cacc[mt][nt], al[mt], bp);
                mma_bf16(cacc[mt][nt], ah[mt], blp);
            }
    }
}

__device__ __forceinline__ void gemm_mainloop(uint32_t sb,
    const __nv_bfloat16* Ah, const __nv_bfloat16* Al,
    const __nv_bfloat16* Bh, const __nv_bfloat16* Bl,
    int m0, int n0, int wm, int wn, int a_r, int a_c8, int b_r, int b_c8,
    float cacc[2][8][4])
{
    gemm_load_stage(sb, Ah, Al, Bh, Bl, m0, n0, 0);
    asm volatile("cp.async.commit_group;" ::: "memory");
    for (int c = 0; c < 32; c++) {
        if (c + 1 < 32) {
            gemm_load_stage(sb + ((c + 1) & 1) * STAGE_B, Ah, Al, Bh, Bl, m0, n0, (c + 1) * 32);
            asm volatile("cp.async.commit_group;" ::: "memory");
            asm volatile("cp.async.wait_group 1;" ::: "memory");
        } else {
            asm volatile("cp.async.wait_group 0;" ::: "memory");
        }
        __syncthreads();
        gemm_compute_stage(sb + (c & 1) * STAGE_B, wm, wn, a_r, a_c8, b_r, b_c8, cacc);
        __syncthreads();
    }
}

// ============================================================================
// GEMM kernel A: QKV projections. z<2 -> q/k bf16 splits; z==2 -> V bf16 splits
// ============================================================================
__global__ void __launch_bounds__(256, 2) gemm_qkv_tc(
    const float* __restrict__ bq, const float* __restrict__ bk, const float* __restrict__ bv)
{
    extern __shared__ __align__(16) char smem[];
    uint32_t sb = smem_u32(smem);
    int z = blockIdx.z;
    int m0 = blockIdx.y * 128, n0 = blockIdx.x * 128;
    const __nv_bfloat16* Ah = g_ah + (size_t)z * M_TOT * E;
    const __nv_bfloat16* Al = g_al + (size_t)z * M_TOT * E;
    const __nv_bfloat16* Bh = g_wth + (size_t)z * E * E;
    const __nv_bfloat16* Bl = g_wtl + (size_t)z * E * E;
    const float* bias = (z == 0) ? bq : (z == 1) ? bk : bv;

    int lane = threadIdx.x & 31, wid = threadIdx.x >> 5;
    int wm = wid & 3, wn = wid >> 2;
    int a_r = lane & 15, a_c8 = (lane >> 4) * 8;
    int b_r = (lane & 7) | ((lane >> 4) << 3), b_c8 = ((lane >> 3) & 1) * 8;

    float cacc[2][8][4] = {};
    gemm_mainloop(sb, Ah, Al, Bh, Bl, m0, n0, wm, wn, a_r, a_c8, b_r, b_c8, cacc);

    __nv_bfloat16* ph;
    __nv_bfloat16* pl;
    if (z == 2) { ph = g_vbh; pl = g_vbl; }
    else { ph = g_pjh + (size_t)z * (BH * S * HD); pl = g_pjl + (size_t)z * (BH * S * HD); }

#pragma unroll
    for (int mt = 0; mt < 2; mt++)
#pragma unroll
        for (int nt = 0; nt < 8; nt++) {
            int m = m0 + wm * 32 + mt * 16 + (lane >> 2);
            int n = n0 + wn * 64 + nt * 8 + (lane & 3) * 2;
            int bb = m >> 10, s = m & 1023, h = n >> 6, d = n & 63;
            size_t base = (((size_t)bb * H + h) * S + s) * HD + d;
            float b0 = bias[n], b1 = bias[n + 1];
            float x0 = cacc[mt][nt][0] + b0, x1 = cacc[mt][nt][1] + b1;
            float x2 = cacc[mt][nt][2] + b0, x3 = cacc[mt][nt][3] + b1;
            __nv_bfloat16 h0 = __float2bfloat16(x0), h1 = __float2bfloat16(x1);
            __nv_bfloat16 h2 = __float2bfloat16(x2), h3 = __float2bfloat16(x3);
            *(__nv_bfloat162*)(ph + base) = __halves2bfloat162(h0, h1);
            *(__nv_bfloat162*)(ph + base + 8 * HD) = __halves2bfloat162(h2, h3);
            *(__nv_bfloat162*)(pl + base) = __halves2bfloat162(
                __float2bfloat16(x0 - __bfloat162float(h0)),
                __float2bfloat16(x1 - __bfloat162float(h1)));
            *(__nv_bfloat162*)(pl + base + 8 * HD) = __halves2bfloat162(
                __float2bfloat16(x2 - __bfloat162float(h2)),
                __float2bfloat16(x3 - __bfloat162float(h3)));
        }
}

// ============================================================================
// GEMM kernel B: output projection -> d_out = AO @ Wo + bo
// ============================================================================
__global__ void __launch_bounds__(256, 2) gemm_out_tc(
    const float* __restrict__ bo, float* __restrict__ dout)
{
    extern __shared__ __align__(16) char smem[];
    uint32_t sb = smem_u32(smem);
    int m0 = blockIdx.y * 128, n0 = blockIdx.x * 128;
    const __nv_bfloat16* Bh = g_wth + (size_t)3 * E * E;
    const __nv_bfloat16* Bl = g_wtl + (size_t)3 * E * E;

    int lane = threadIdx.x & 31, wid = threadIdx.x >> 5;
    int wm = wid & 3, wn = wid >> 2;
    int a_r = lane & 15, a_c8 = (lane >> 4) * 8;
    int b_r = (lane & 7) | ((lane >> 4) << 3), b_c8 = ((lane >> 3) & 1) * 8;

    float cacc[2][8][4] = {};
    gemm_mainloop(sb, g_aoh, g_aol, Bh, Bl, m0, n0, wm, wn, a_r, a_c8, b_r, b_c8, cacc);

#pragma unroll
    for (int mt = 0; mt < 2; mt++)
#pragma unroll
        for (int nt = 0; nt < 8; nt++) {
            int m = m0 + wm * 32 + mt * 16 + (lane >> 2);
            int n = n0 + wn * 64 + nt * 8 + (lane & 3) * 2;
            float* op = dout + (size_t)m * E + n;
            float b0 = bo[n], b1 = bo[n + 1];
            *(float2*)op = make_float2(cacc[mt][nt][0] + b0, cacc[mt][nt][1] + b1);
            *(float2*)(op + 8 * E) = make_float2(cacc[mt][nt][2] + b0, cacc[mt][nt][3] + b1);
        }
}

// ============================================================================
// logits via mma (lower-tri tiles)
// ============================================================================
#define LPITCH 72
#define LTILE_B (128 * LPITCH * 2)   // 18432
#define LOG_SMEM (4 * LTILE_B)       // 73728

__global__ void __launch_bounds__(256, 2) logits_mma_kernel()
{
    extern __shared__ __align__(16) char smem[];
    uint32_t sb = smem_u32(smem);
    const int bh = blockIdx.y;
    int t = blockIdx.x, r = 0;
    while (t > r) { t -= r + 1; r++; }
    const int row0 = r * 128;
    const int col0 = t * 128;

    const __nv_bfloat16* Qh = g_pjh + (size_t)bh * S * HD;
    const __nv_bfloat16* Ql = g_pjl + (size_t)bh * S * HD;
    const __nv_bfloat16* Kh = g_pjh + (size_t)(BH + bh) * S * HD;
    const __nv_bfloat16* Kl = g_pjl + (size_t)(BH + bh) * S * HD;
    float* L = g_logits + (size_t)bh * S * S;

    int tid = threadIdx.x, lane = tid & 31, wid = tid >> 5;
    int wm = wid & 3, wn = wid >> 2;
    int a_r = lane & 15, a_c8 = (lane >> 4) * 8;
    int b_r = (lane & 7) | ((lane >> 4) << 3), b_c8 = ((lane >> 3) & 1) * 8;

#pragma unroll
    for (int i = 0; i < 4; i++) {
        int idx = tid + i * 256;
        int rr = idx >> 3, cc = (idx & 7) * 8;
        uint32_t so = (uint32_t)(rr * LPITCH + cc) * 2;
        cp16(sb + so,               Qh + (size_t)(row0 + rr) * HD + cc);
        cp16(sb + LTILE_B + so,     Ql + (size_t)(row0 + rr) * HD + cc);
        cp16(sb + 2 * LTILE_B + so, Kh + (size_t)(col0 + rr) * HD + cc);
        cp16(sb + 3 * LTILE_B + so, Kl + (size_t)(col0 + rr) * HD + cc);
    }
    asm volatile("cp.async.commit_group;" ::: "memory");
    asm volatile("cp.async.wait_group 0;" ::: "memory");
    __syncthreads();

    float cacc[2][8][4] = {};
#pragma unroll
    for (int kk = 0; kk < 64; kk += 16) {
        uint32_t ah[2][4], al[2][4], bhf[4][4], blf[4][4];
#pragma unroll
        for (int mt = 0; mt < 2; mt++) {
            uint32_t ro = (uint32_t)((wm * 32 + mt * 16 + a_r) * LPITCH + kk + a_c8) * 2;
            ldsm_x4(ah[mt], sb + ro);
            ldsm_x4(al[mt], sb + LTILE_B + ro);
        }
#pragma unroll
        for (int i = 0; i < 4; i++) {
            uint32_t ro = (uint32_t)((wn * 64 + i * 16 + b_r) * LPITCH + kk + b_c8) * 2;
            ldsm_x4(bhf[i], sb + 2 * LTILE_B + ro);
            ldsm_x4(blf[i], sb + 3 * LTILE_B + ro);
        }
#pragma unroll
        for (int mt = 0; mt < 2; mt++)
#pragma unroll
            for (int nt = 0; nt < 8; nt++) {
                const uint32_t* bp  = &bhf[nt >> 1][(nt & 1) * 2];
                const uint32_t* blp = &blf[nt >> 1][(nt & 1) * 2];
                mma_bf16(cacc[mt][nt], ah[mt], bp);
                mma_bf16(cacc[mt][nt], al[mt], bp);
                mma_bf16(cacc[mt][nt], ah[mt], blp);
            }
    }

    const float scale = 0.125f;
#pragma unroll
    for (int mt = 0; mt < 2; mt++)
#pragma unroll
        for (int nt = 0; nt < 8; nt++) {
            int m = row0 + wm * 32 + mt * 16 + (lane >> 2);
            int n = col0 + wn * 64 + nt * 8 + (lane & 3) * 2;
            float2 v0, v1;
            v0.x = (n     <= m) ? cacc[mt][nt][0] * scale : 0.f;
            v0.y = (n + 1 <= m) ? cacc[mt][nt][1] * scale : 0.f;
            v1.x = (n     <= m + 8) ? cacc[mt][nt][2] * scale : 0.f;
            v1.y = (n + 1 <= m + 8) ? cacc[mt][nt][3] * scale : 0.f;
            *(float2*)&L[(size_t)m * S + n] = v0;
            *(float2*)&L[(size_t)(m + 8) * S + n] = v1;
        }
}

// ============================================================================
// conv + softmax, HEAD-PAIR per block -> writes MIXED bf16 hi/lo splits
// ============================================================================
__device__ __forceinline__ void conv_load_row2(
    const float* __restrict__ L0, const float* __restrict__ L1, int qp, int c, int tid,
    float* sx0, float* sw0, float* sx1, float* sw1, float r0[6], float r1[6])
{
    float4 v0 = make_float4(0.f, 0.f, 0.f, 0.f);
    float4 v1 = v0;
    if (qp >= 0 && c <= qp) {
        v0 = *(const float4*)&L0[(size_t)qp * S + c];
        v1 = *(const float4*)&L1[(size_t)qp * S + c];
        if (c + 1 > qp) { v0.y = 0.f; v1.y = 0.f; }
        if (c + 2 > qp) { v0.z = 0.f; v1.z = 0.f; }
        if (c + 3 > qp) { v0.w = 0.f; v1.w = 0.f; }
    }
    __syncthreads();               // WAR: previous row's halo + ss reads done
    sx0[tid] = v0.x; sw0[tid] = v0.w;
    sx1[tid] = v1.x; sw1[tid] = v1.w;
    __syncthreads();
    r0[0] = (tid > 0) ? sw0[tid - 1] : 0.f;
    r0[1] = v0.x; r0[2] = v0.y; r0[3] = v0.z; r0[4] = v0.w;
    r0[5] = (tid < 255) ? sx0[tid + 1] : 0.f;
    r1[0] = (tid > 0) ? sw1[tid - 1] : 0.f;
    r1[1] = v1.x; r1[2] = v1.y; r1[3] = v1.z; r1[4] = v1.w;
    r1[5] = (tid < 255) ? sx1[tid + 1] : 0.f;
}

#define QROWS 8
__global__ __launch_bounds__(256) void conv_softmax_kernel(
    const float* __restrict__ kq_w, const float* __restrict__ kq_b,
    const float* __restrict__ mix_w)
{
    const int pb = blockIdx.y;               // pair index 0..15
    const int b = pb >> 3, hp = pb & 7;
    const int h0 = hp * 2, h1 = h0 + 1;
    const int bh0 = b * 16 + h0, bh1 = bh0 + 1;
    const int q0 = blockIdx.x * QROWS;
    const float* L0 = g_logits + (size_t)bh0 * S * S;
    const float* L1 = g_logits + (size_t)bh1 * S * S;

    __shared__ float sx0[256], sw0[256], sx1[256], sw1[256], ss0[8], ss1[8];
    const int tid = threadIdx.x;
    const int lane = tid & 31, wrp = tid >> 5;
    const int c = tid * 4;

    float wv0[9], wv1[9];
#pragma unroll
    for (int t = 0; t < 9; t++) { wv0[t] = kq_w[h0 * 9 + t]; wv1[t] = kq_w[h1 * 9 + t]; }
    const float bias0 = kq_b[h0], bias1 = kq_b[h1];
    const float eb0 = __expf(bias0), eb1 = __expf(bias1);
    const float m00 = mix_w[h0 * 2 + 0], m01 = mix_w[h0 * 2 + 1];
    const float m10 = mix_w[h1 * 2 + 0], m11 = mix_w[h1 * 2 + 1];

    float ra0[6], rb0[6], rc0[6], ra1[6], rb1[6], rc1[6];
    conv_load_row2(L0, L1, q0 - 2, c, tid, sx0, sw0, sx1, sw1, ra0, ra1);
    conv_load_row2(L0, L1, q0 - 1, c, tid, sx0, sw0, sx1, sw1, rb0, rb1);

    for (int i = 0; i < QROWS; i++) {
        const int q = q0 + i;
        conv_load_row2(L0, L1, q, c, tid, sx0, sw0, sx1, sw1, rc0, rc1);
        const int kmax = (q + 1 < S - 1) ? (q + 1) : (S - 1);

        float e0[4], e1[4];
        float es0 = 0.f, es1 = 0.f;
#pragma unroll
        for (int u = 0; u < 4; u++) {
            if (c + u <= kmax) {
                float c0 = wv0[0] * ra0[u] + wv0[1] * ra0[u + 1] + wv0[2] * ra0[u + 2]
                         + wv0[3] * rb0[u] + wv0[4] * rb0[u + 1] + wv0[5] * rb0[u + 2]
                         + wv0[6] * rc0[u] + wv0[7] * rc0[u + 1] + wv0[8] * rc0[u + 2] + bias0;
                float c1 = wv1[0] * ra1[u] + wv1[1] * ra1[u + 1] + wv1[2] * ra1[u + 2]
                         + wv1[3] * rb1[u] + wv1[4] * rb1[u + 1] + wv1[5] * rb1[u + 2]
                         + wv1[6] * rc1[u] + wv1[7] * rc1[u + 1] + wv1[8] * rc1[u + 2] + bias1;
                e0[u] = __expf(c0); es0 += e0[u];
                e1[u] = __expf(c1); es1 += e1[u];
            } else { e0[u] = 0.f; e1[u] = 0.f; }
        }
        float s0 = es0, s1 = es1;
#pragma unroll
        for (int o = 16; o; o >>= 1) {
            s0 += __shfl_xor_sync(0xffffffffu, s0, o);
            s1 += __shfl_xor_sync(0xffffffffu, s1, o);
        }
        if (lane == 0) { ss0[wrp] = s0; ss1[wrp] = s1; }
        __syncthreads();
        float t0 = ss0[lane & 7], t1 = ss1[lane & 7];
#pragma unroll
        for (int o = 4; o; o >>= 1) {
            t0 += __shfl_xor_sync(0xffffffffu, t0, o);
            t1 += __shfl_xor_sync(0xffffffffu, t1, o);
        }

        int cnt = S - 2 - q; if (cnt < 0) cnt = 0;
        float inv0 = 1.f / (t0 + (float)cnt * eb0);
        float inv1 = 1.f / (t1 + (float)cnt * eb1);
        float c0v = eb0 * inv0, c1v = eb1 * inv1;
        float cm0 = m00 * c0v + m01 * c1v;   // mixed const for output head h0
        float cm1 = m10 * c0v + m11 * c1v;   // mixed const for output head h1
        if (tid == 0) {
            g_rowconst[bh0 * S + q] = cm0;
            g_rowconst[bh1 * S + q] = cm1;
        }

        int Klim = ((q >> 6) << 6) + 128; if (Klim > S) Klim = S;
        if (c < Klim) {
            float a0[4], a1[4], x0[4], x1[4];
#pragma unroll
            for (int u = 0; u < 4; u++) {
                a0[u] = (c + u <= kmax) ? e0[u] * inv0 : c0v;
                a1[u] = (c + u <= kmax) ? e1[u] * inv1 : c1v;
                x0[u] = m00 * a0[u] + m01 * a1[u];
                x1[u] = m10 * a0[u] + m11 * a1[u];
            }
            size_t off0 = (size_t)bh0 * S * S + (size_t)q * S + c;
            size_t off1 = (size_t)bh1 * S * S + (size_t)q * S + c;
            split_store4g(g_mxh + off0, g_mxl + off0, x0);
            split_store4g(g_mxh + off1, g_mxl + off1, x1);
        }

#pragma unroll
        for (int u = 0; u < 6; u++) {
            ra0[u] = rb0[u]; rb0[u] = rc0[u];
            ra1[u] = rb1[u]; rb1[u] = rc1[u];
        }
    }
}

// ============================================================================
// V chunk sums (from bf16 hi/lo) + parallel suffix
// ============================================================================
__global__ __launch_bounds__(256) void vchunk_kernel()
{
    const int bh = blockIdx.x, ci = blockIdx.y;
    const int tid = threadIdx.x;
    const int d = tid & 63, rg = tid >> 6;
    const __nv_bfloat16* Vh = g_vbh + (size_t)bh * S * HD;
    const __nv_bfloat16* Vl = g_vbl + (size_t)bh * S * HD;
    float s = 0.f;
#pragma unroll
    for (int r = 0; r < 16; r++) {
        size_t o = (size_t)(ci * 64 + rg * 16 + r) * HD + d;
        s += __bfloat162float(Vh[o]) + __bfloat162float(Vl[o]);
    }
    __shared__ float sm[4][64];
    sm[rg][d] = s;
    __syncthreads();
    if (tid < 64)
        g_chunkV[((size_t)bh * 16 + ci) * HD + tid] = sm[0][tid] + sm[1][tid] + sm[2][tid] + sm[3][tid];
}

__global__ __launch_bounds__(256) void vsuffix_kernel()
{
    const int bh = blockIdx.x;
    const float* ch = g_chunkV + (size_t)bh * 16 * HD;
    for (int idx = threadIdx.x; idx < 17 * HD; idx += 256) {
        int ci = idx >> 6, d = idx & 63;
        float suf = 0.f;
        for (int j = 15; j >= ci; j--) suf += ch[j * HD + d];
        g_suffV[((size_t)bh * 17 + ci) * HD + d] = suf;
    }
}

// ============================================================================
// pv via mma: A = pre-mixed bf16 splits (cp.async), B = V splits (trans ldsm)
// ============================================================================
#define PV_APITCH 40
#define PV_VPITCH 136
#define PV_ATILE (64 * PV_APITCH * 2)          // 5120
#define PV_VTILE (32 * PV_VPITCH * 2)          // 8704
#define PV_STAGE (4 * PV_ATILE + 2 * PV_VTILE) // 37888
#define PV_SMEM (2 * PV_STAGE)                 // 75776

__device__ __forceinline__ void pv_load_stage(uint32_t sb, int stage,
    const __nv_bfloat16* __restrict__ A0h, const __nv_bfloat16* __restrict__ A0l,
    const __nv_bfloat16* __restrict__ A1h, const __nv_bfloat16* __restrict__ A1l,
    const __nv_bfloat16* __restrict__ V0h, const __nv_bfloat16* __restrict__ V0l,
    const __nv_bfloat16* __restrict__ V1h, const __nv_bfloat16* __restrict__ V1l,
    int k0)
{
    const int tid = threadIdx.x;
    uint32_t base = sb + stage * PV_STAGE;
    {
        int r = tid >> 2, ch = tid & 3;
        uint32_t so = (uint32_t)(r * PV_APITCH * 2 + ch * 16);
        size_t go = (size_t)r * S + k0 + ch * 8;
        cp16(base + so,                A0h + go);
        cp16(base + PV_ATILE + so,     A0l + go);
        cp16(base + 2 * PV_ATILE + so, A1h + go);
        cp16(base + 3 * PV_ATILE + so, A1l + go);
    }
    uint32_t vbase = base + 4 * PV_ATILE;
#pragma unroll
    for (int i = 0; i < 2; i++) {
        int idx = tid + i * 256;
        int r = idx >> 4, ch = idx & 15;
        uint32_t so = (uint32_t)(r * PV_VPITCH * 2 + ch * 16);
        size_t go = (size_t)(k0 + r) * HD;
        if (ch < 8) {
            cp16(vbase + so,            V0h + go + ch * 8);
            cp16(vbase + PV_VTILE + so, V0l + go + ch * 8);
        } else {
            cp16(vbase + so,            V1h + go + (ch - 8) * 8);
            cp16(vbase + PV_VTILE + so, V1l + go + (ch - 8) * 8);
        }
    }
}

__global__ void __launch_bounds__(256, 2) pv_mma_kernel(
    const float* __restrict__ mix_b,
    const float* __restrict__ dyt_alpha, const float* __restrict__ dyt_w,
    const float* __restrict__ dyt_b, const float* __restrict__ depth_scale)
{
    extern __shared__ __align__(16) char smem[];
    uint32_t sb = smem_u32(smem);
    const int pair = blockIdx.z;
    const int b = pair >> 3, hp = pair & 7;
    const int h0 = hp * 2, h1 = h0 + 1;
    const int bh0 = b * 16 + h0, bh1 = bh0 + 1;
    const int Q0 = (gridDim.y - 1 - blockIdx.y) * 64;
    int Klim = Q0 + 128; if (Klim > S) Klim = S;
    const int cidx = Klim >> 6;
    const int nch = Klim >> 5;

    const __nv_bfloat16* A0h = g_mxh + (size_t)bh0 * S * S + (size_t)Q0 * S;
    const __nv_bfloat16* A0l = g_mxl + (size_t)bh0 * S * S + (size_t)Q0 * S;
    const __nv_bfloat16* A1h = g_mxh + (size_t)bh1 * S * S + (size_t)Q0 * S;
    const __nv_bfloat16* A1l = g_mxl + (size_t)bh1 * S * S + (size_t)Q0 * S;
    const __nv_bfloat16* V0h = g_vbh + (size_t)bh0 * S * HD;
    const __nv_bfloat16* V0l = g_vbl + (size_t)bh0 * S * HD;
    const __nv_bfloat16* V1h = g_vbh + (size_t)bh1 * S * HD;
    const __nv_bfloat16* V1l = g_vbl + (size_t)bh1 * S * HD;

    const int tid = threadIdx.x, lane = tid & 31, wid = tid >> 5;
    const int wm = wid & 3, wn = wid >> 2;
    const int a_r = lane & 15, a_c8 = (lane >> 4) * 8;
    const int bt_r = lane & 15, bt_c8 = (lane >> 4) * 8;

    float acc[8][4] = {};

    pv_load_stage(sb, 0, A0h, A0l, A1h, A1l, V0h, V0l, V1h, V1l, 0);
    asm volatile("cp.async.commit_group;" ::: "memory");

    for (int c = 0; c < nch; c++) {
        if (c + 1 < nch) {
            pv_load_stage(sb, (c + 1) & 1, A0h, A0l, A1h, A1l, V0h, V0l, V1h, V1l, (c + 1) * 32);
            asm volatile("cp.async.commit_group;" ::: "memory");
            asm volatile("cp.async.wait_group 1;" ::: "memory");
        } else {
            asm volatile("cp.async.wait_group 0;" ::: "memory");
        }
        __syncthreads();
        uint32_t base = sb + (c & 1) * PV_STAGE;
        uint32_t sAh = base + (wn * 2) * PV_ATILE;
        uint32_t sAl = base + (wn * 2 + 1) * PV_ATILE;
        uint32_t sVh = base + 4 * PV_ATILE;
        uint32_t sVl = sVh + PV_VTILE;
#pragma unroll
        for (int kk = 0; kk < 32; kk += 16) {
            uint32_t ah[4], al[4];
            uint32_t ro = (uint32_t)((wm * 16 + a_r) * PV_APITCH + kk + a_c8) * 2;
            ldsm_x4(ah, sAh + ro);
            ldsm_x4(al, sAl + ro);
            uint32_t bhf[4][4], blf[4][4];
#pragma unroll
            for (int t = 0; t < 4; t++) {
                uint32_t vo = (uint32_t)((kk + bt_r) * PV_VPITCH + wn * 64 + t * 16 + bt_c8) * 2;
                ldsm_x4_t(bhf[t], sVh + vo);
                ldsm_x4_t(blf[t], sVl + vo);
            }
#pragma unroll
            for (int nt = 0; nt < 8; nt++) {
                const uint32_t* bp  = &bhf[nt >> 1][(nt & 1) * 2];
                const uint32_t* blp = &blf[nt >> 1][(nt & 1) * 2];
                mma_bf16(acc[nt], ah, bp);
                mma_bf16(acc[nt], al, bp);
                mma_bf16(acc[nt], ah, blp);
            }
        }
        __syncthreads();
    }

    const int bhh = wn ? bh1 : bh0;
    const float* suff = g_suffV + ((size_t)bhh * 17 + cidx) * HD;
    const float* csum = g_suffV + ((size_t)bhh * 17 + 0) * HD;
    const float* rcm = g_rowconst + bhh * S;
    const float mb = mix_b[wn ? h1 : h0];
    const float alpha = dyt_alpha[0], ds = depth_scale[0];
    const int q0r = Q0 + wm * 16 + (lane >> 2);
    const float cm0 = rcm[q0r];
    const float cm1 = rcm[q0r + 8];
    __nv_bfloat16* Oh = g_aoh + (size_t)b * S * E + h0 * HD;
    __nv_bfloat16* Ol = g_aol + (size_t)b * S * E + h0 * HD;

#pragma unroll
    for (int nt = 0; nt < 8; nt++) {
        int d = wn * 64 + nt * 8 + (lane & 3) * 2;
        int dl = d & 63;
        float sw0 = suff[dl], sw1 = suff[dl + 1];
        float cs0 = csum[dl], cs1 = csum[dl + 1];
        float w0 = dyt_w[dl], w1 = dyt_w[dl + 1];
        float bb0 = dyt_b[dl], bb1 = dyt_b[dl + 1];
#pragma unroll
        for (int half = 0; half < 2; half++) {
            int q = q0r + half * 8;
            float cm = half ? cm1 : cm0;
            float v0 = acc[nt][half * 2 + 0] + cm * sw0 + mb * cs0;
            float v1 = acc[nt][half * 2 + 1] + cm * sw1 + mb * cs1;
            v0 = (tanhf(alpha * v0) * w0 + bb0) * ds;
            v1 = (tanhf(alpha * v1) * w1 + bb1) * ds;
            __nv_bfloat16 h0v = __float2bfloat16(v0), h1v = __float2bfloat16(v1);
            *(__nv_bfloat162*)&Oh[(size_t)q * E + d] = __halves2bfloat162(h0v, h1v);
            *(__nv_bfloat162*)&Ol[(size_t)q * E + d] = __halves2bfloat162(
                __float2bfloat16(v0 - __bfloat162float(h0v)),
                __float2bfloat16(v1 - __bfloat162float(h1v)));
        }
    }
}

// ============================================================================
// Launch  (R13 order restored)
// ============================================================================
extern "C" void kernel_launch(void* const* d_in, const int* in_sizes, int n_in,
                              void* d_out, int out_size)
{
    const float* Q   = (const float*)d_in[0];
    const float* K   = (const float*)d_in[1];
    const float* V   = (const float*)d_in[2];
    const float* Wq  = (const float*)d_in[3];
    const float* bq  = (const float*)d_in[4];
    const float* Wk  = (const float*)d_in[5];
    const float* bk  = (const float*)d_in[6];
    const float* Wv  = (const float*)d_in[7];
    const float* bv  = (const float*)d_in[8];
    const float* Wo  = (const float*)d_in[9];
    const float* bo  = (const float*)d_in[10];
    const float* kq_w = (const float*)d_in[11];
    const float* kq_b = (const float*)d_in[12];
    const float* mix_w = (const float*)d_in[13];
    const float* mix_b = (const float*)d_in[14];
    const float* dyt_alpha = (const float*)d_in[15];
    const float* dyt_w = (const float*)d_in[16];
    const float* dyt_b = (const float*)d_in[17];
    const float* depth_scale = (const float*)d_in[18];

    cudaFuncSetAttribute(gemm_qkv_tc, cudaFuncAttributeMaxDynamicSharedMemorySize, GEMM_SMEM);
    cudaFuncSetAttribute(gemm_out_tc, cudaFuncAttributeMaxDynamicSharedMemorySize, GEMM_SMEM);
    cudaFuncSetAttribute(logits_mma_kernel, cudaFuncAttributeMaxDynamicSharedMemorySize, LOG_SMEM);
    cudaFuncSetAttribute(pv_mma_kernel, cudaFuncAttributeMaxDynamicSharedMemorySize, PV_SMEM);

    asplit_kernel<<<dim3(2048, 1, 3), 256>>>(Q, K, V);
    wsplit_kernel<<<dim3(32, 32, 4), dim3(32, 8)>>>(Wq, Wk, Wv, Wo);
    gemm_qkv_tc<<<dim3(8, 16, 3), 256, GEMM_SMEM>>>(bq, bk, bv);
    vchunk_kernel<<<dim3(BH, 16), 256>>>();
    vsuffix_kernel<<<BH, 256>>>();
    logits_mma_kernel<<<dim3(36, BH), 256, LOG_SMEM>>>();
    conv_softmax_kernel<<<dim3(S / QROWS, BH / 2), 256>>>(kq_w, kq_b, mix_w);
    pv_mma_kernel<<<dim3(1, S / 64, BH / 2), 256, PV_SMEM>>>(mix_b, dyt_alpha, dyt_w, dyt_b, depth_scale);
    gemm_out_tc<<<dim3(8, 16), 256, GEMM_SMEM>>>(bo, (float*)d_out);
}

// round 16
// speedup vs baseline: 1.5512x; 1.0206x over previous
#include <cuda_runtime.h>
#include <cuda_bf16.h>
#include <math.h>
#include <cstdint>

#define S 1024
#define E 1024
#define H 16
#define HD 64
#define BATCH 2
#define BH (BATCH * H)     // 32
#define M_TOT (BATCH * S)  // 2048

// ---------------- scratch (device globals; no runtime allocation) ----------
__device__ __align__(16) float g_logits[BH * S * S];
__device__ __align__(16) float g_rowconst[BH * S];          // MIXED row consts
__device__ __align__(16) float g_suffV[BH * 17 * HD];
__device__ __align__(16) __nv_bfloat16 g_mxh[BH * S * S];   // mixed attn hi
__device__ __align__(16) __nv_bfloat16 g_mxl[BH * S * S];   // mixed attn lo
__device__ __align__(16) __nv_bfloat16 g_ah[3 * M_TOT * E];
__device__ __align__(16) __nv_bfloat16 g_al[3 * M_TOT * E];
__device__ __align__(16) __nv_bfloat16 g_wth[4 * E * E];   // W^T [n][k]
__device__ __align__(16) __nv_bfloat16 g_wtl[4 * E * E];
__device__ __align__(16) __nv_bfloat16 g_aoh[M_TOT * E];
__device__ __align__(16) __nv_bfloat16 g_aol[M_TOT * E];
__device__ __align__(16) __nv_bfloat16 g_pjh[2 * BH * S * HD];  // q,k hi
__device__ __align__(16) __nv_bfloat16 g_pjl[2 * BH * S * HD];  // q,k lo
__device__ __align__(16) __nv_bfloat16 g_vbh[BH * S * HD];      // V hi
__device__ __align__(16) __nv_bfloat16 g_vbl[BH * S * HD];      // V lo

// ============================ PTX helpers ===================================
__device__ __forceinline__ uint32_t smem_u32(const void* p) {
    uint32_t a;
    asm("{ .reg .u64 t; cvta.to.shared.u64 t, %1; cvt.u32.u64 %0, t; }" : "=r"(a) : "l"(p));
    return a;
}
__device__ __forceinline__ void ldsm_x4(uint32_t* r, uint32_t addr) {
    asm volatile("ldmatrix.sync.aligned.m8n8.x4.shared.b16 {%0,%1,%2,%3}, [%4];"
        : "=r"(r[0]), "=r"(r[1]), "=r"(r[2]), "=r"(r[3]) : "r"(addr));
}
__device__ __forceinline__ void ldsm_x4_t(uint32_t* r, uint32_t addr) {
    asm volatile("ldmatrix.sync.aligned.m8n8.x4.trans.shared.b16 {%0,%1,%2,%3}, [%4];"
        : "=r"(r[0]), "=r"(r[1]), "=r"(r[2]), "=r"(r[3]) : "r"(addr));
}
__device__ __forceinline__ void mma_bf16(float* c, const uint32_t* a, const uint32_t* b) {
    asm volatile("mma.sync.aligned.m16n8k16.row.col.f32.bf16.bf16.f32 "
        "{%0,%1,%2,%3}, {%4,%5,%6,%7}, {%8,%9}, {%0,%1,%2,%3};"
        : "+f"(c[0]), "+f"(c[1]), "+f"(c[2]), "+f"(c[3])
        : "r"(a[0]), "r"(a[1]), "r"(a[2]), "r"(a[3]), "r"(b[0]), "r"(b[1]));
}
__device__ __forceinline__ void cp16(uint32_t saddr, const void* g) {
    asm volatile("cp.async.cg.shared.global [%0], [%1], 16;" :: "r"(saddr), "l"(g));
}
__device__ __forceinline__ void cp16ca(uint32_t saddr, const void* g) {
    asm volatile("cp.async.ca.shared.global [%0], [%1], 16;" :: "r"(saddr), "l"(g));
}
// split f32x4 -> one 8B hi store + one 8B lo store (gmem)
__device__ __forceinline__ void split_store4g(__nv_bfloat16* hp, __nv_bfloat16* lp, const float* x) {
    __nv_bfloat16 h0 = __float2bfloat16(x[0]), h1 = __float2bfloat16(x[1]);
    __nv_bfloat16 h2 = __float2bfloat16(x[2]), h3 = __float2bfloat16(x[3]);
    __nv_bfloat162 a = __halves2bfloat162(h0, h1), b = __halves2bfloat162(h2, h3);
    uint2 hv; hv.x = *(uint32_t*)&a; hv.y = *(uint32_t*)&b;
    *(uint2*)hp = hv;
    __nv_bfloat162 c = __halves2bfloat162(
        __float2bfloat16(x[0] - __bfloat162float(h0)),
        __float2bfloat16(x[1] - __bfloat162float(h1)));
    __nv_bfloat162 d = __halves2bfloat162(
        __float2bfloat16(x[2] - __bfloat162float(h2)),
        __float2bfloat16(x[3] - __bfloat162float(h3)));
    uint2 lv; lv.x = *(uint32_t*)&c; lv.y = *(uint32_t*)&d;
    *(uint2*)lp = lv;
}

// GEMM geometry: 128x128 block, BK=32, 8 warps (4m x 2n), warp 32x64.
#define PITCH 40                 // bf16 per smem row (80 B: conflict-free ldmatrix)
#define TILE_B 10240             // 128 * PITCH * 2
#define STAGE_B 40960            // 4 tiles (Ah, Al, Bh, Bl)
#define GEMM_SMEM (2 * STAGE_B)  // 81920

// ============================================================================
// prep: split f32 -> bf16 hi/lo (Q, K, V inputs)
// ============================================================================
__global__ __launch_bounds__(256) void asplit_kernel(
    const float* __restrict__ Q, const float* __restrict__ K, const float* __restrict__ V)
{
    int z = blockIdx.z;
    const float* X = (z == 0) ? Q : (z == 1) ? K : V;
    __nv_bfloat16* hp = g_ah + (size_t)z * M_TOT * E;
    __nv_bfloat16* lp = g_al + (size_t)z * M_TOT * E;
    int i = (blockIdx.x * 256 + threadIdx.x) * 4;
    float4 v = *(const float4*)(X + i);
    float vv[4] = {v.x, v.y, v.z, v.w};
#pragma unroll
    for (int j = 0; j < 4; j++) {
        __nv_bfloat16 h = __float2bfloat16(vv[j]);
        hp[i + j] = h;
        lp[i + j] = __float2bfloat16(vv[j] - __bfloat162float(h));
    }
}

// ============================================================================
// prep: transpose + split weights: Wt[n][k] = W[k][n], bf16 hi/lo
// ============================================================================
__global__ void wsplit_kernel(const float* __restrict__ Wq, const float* __restrict__ Wk,
                              const float* __restrict__ Wv, const float* __restrict__ Wo)
{
    int z = blockIdx.z;
    const float* W = (z == 0) ? Wq : (z == 1) ? Wk : (z == 2) ? Wv : Wo;
    __nv_bfloat16* th = g_wth + (size_t)z * E * E;
    __nv_bfloat16* tl = g_wtl + (size_t)z * E * E;
    __shared__ float tile[32][33];
    int n0 = blockIdx.x * 32, k0 = blockIdx.y * 32;
    int tx = threadIdx.x, ty = threadIdx.y;
    for (int i = ty; i < 32; i += 8)
        tile[i][tx] = W[(size_t)(k0 + i) * E + n0 + tx];
    __syncthreads();
    for (int i = ty; i < 32; i += 8) {
        float v = tile[tx][i];
        __nv_bfloat16 h = __float2bfloat16(v);
        th[(size_t)(n0 + i) * E + k0 + tx] = h;
        tl[(size_t)(n0 + i) * E + k0 + tx] = __float2bfloat16(v - __bfloat162float(h));
    }
}

// ============================================================================
// mma.sync GEMM core (E-deep, pipelined); weights via .ca (L1-cached)
// ============================================================================
__device__ __forceinline__ void gemm_load_stage(uint32_t sbs,
    const __nv_bfloat16* __restrict__ Ah, const __nv_bfloat16* __restrict__ Al,
    const __nv_bfloat16* __restrict__ Bh, const __nv_bfloat16* __restrict__ Bl,
    int m0, int n0, int k0)
{
    int t = threadIdx.x;
#pragma unroll
    for (int i = 0; i < 2; i++) {
        int idx = t + i * 256;
        int r = idx >> 2, c = (idx & 3) * 8;
        uint32_t so = (uint32_t)(r * PITCH + c) * 2;
        cp16(sbs + so,              Ah + (size_t)(m0 + r) * E + k0 + c);
        cp16(sbs + TILE_B + so,     Al + (size_t)(m0 + r) * E + k0 + c);
        cp16ca(sbs + 2 * TILE_B + so, Bh + (size_t)(n0 + r) * E + k0 + c);
        cp16ca(sbs + 3 * TILE_B + so, Bl + (size_t)(n0 + r) * E + k0 + c);
    }
}

__device__ __forceinline__ void gemm_compute_stage(
    uint32_t sb, int wm, int wn, int a_r, int a_c8, int b_r, int b_c8,
    float cacc[2][8][4])
{
#pragma unroll
    for (int kk = 0; kk < 32; kk += 16) {
        uint32_t ah[2][4], al[2][4], bh[4][4], bl[4][4];
#pragma unroll
        for (int mt = 0; mt < 2; mt++) {
            uint32_t ro = (uint32_t)((wm * 32 + mt * 16 + a_r) * PITCH + kk + a_c8) * 2;
            ldsm_x4(ah[mt], sb + ro);
            ldsm_x4(al[mt], sb + TILE_B + ro);
        }
#pragma unroll
        for (int i = 0; i < 4; i++) {
            uint32_t ro = (uint32_t)((wn * 64 + i * 16 + b_r) * PITCH + kk + b_c8) * 2;
            ldsm_x4(bh[i], sb + 2 * TILE_B + ro);
            ldsm_x4(bl[i], sb + 3 * TILE_B + ro);
        }
#pragma unroll
        for (int mt = 0; mt < 2; mt++)
#pragma unroll
            for (int nt = 0; nt < 8; nt++) {
                const uint32_t* bp  = &bh[nt >> 1][(nt & 1) * 2];
                const uint32_t* blp = &bl[nt >> 1][(nt & 1) * 2];
                mma_bf16(cacc[mt][nt], ah[mt], bp);
                mma_bf16(cacc[mt][nt], al[mt], bp);
                mma_bf16(cacc[mt][nt], ah[mt], blp);
            }
    }
}

__device__ __forceinline__ void gemm_mainloop(uint32_t sb,
    const __nv_bfloat16* Ah, const __nv_bfloat16* Al,
    const __nv_bfloat16* Bh, const __nv_bfloat16* Bl,
    int m0, int n0, int wm, int wn, int a_r, int a_c8, int b_r, int b_c8,
    float cacc[2][8][4])
{
    gemm_load_stage(sb, Ah, Al, Bh, Bl, m0, n0, 0);
    asm volatile("cp.async.commit_group;" ::: "memory");
    for (int c = 0; c < 32; c++) {
        if (c + 1 < 32) {
            gemm_load_stage(sb + ((c + 1) & 1) * STAGE_B, Ah, Al, Bh, Bl, m0, n0, (c + 1) * 32);
            asm volatile("cp.async.commit_group;" ::: "memory");
            asm volatile("cp.async.wait_group 1;" ::: "memory");
        } else {
            asm volatile("cp.async.wait_group 0;" ::: "memory");
        }
        __syncthreads();
        gemm_compute_stage(sb + (c & 1) * STAGE_B, wm, wn, a_r, a_c8, b_r, b_c8, cacc);
        __syncthreads();
    }
}

// ============================================================================
// GEMM kernel A: QKV projections. z<2 -> q/k bf16 splits; z==2 -> V bf16 splits
// ============================================================================
__global__ void __launch_bounds__(256, 2) gemm_qkv_tc(
    const float* __restrict__ bq, const float* __restrict__ bk, const float* __restrict__ bv)
{
    extern __shared__ __align__(16) char smem[];
    uint32_t sb = smem_u32(smem);
    int z = blockIdx.z;
    int m0 = blockIdx.y * 128, n0 = blockIdx.x * 128;
    const __nv_bfloat16* Ah = g_ah + (size_t)z * M_TOT * E;
    const __nv_bfloat16* Al = g_al + (size_t)z * M_TOT * E;
    const __nv_bfloat16* Bh = g_wth + (size_t)z * E * E;
    const __nv_bfloat16* Bl = g_wtl + (size_t)z * E * E;
    const float* bias = (z == 0) ? bq : (z == 1) ? bk : bv;

    int lane = threadIdx.x & 31, wid = threadIdx.x >> 5;
    int wm = wid & 3, wn = wid >> 2;
    int a_r = lane & 15, a_c8 = (lane >> 4) * 8;
    int b_r = (lane & 7) | ((lane >> 4) << 3), b_c8 = ((lane >> 3) & 1) * 8;

    float cacc[2][8][4] = {};
    gemm_mainloop(sb, Ah, Al, Bh, Bl, m0, n0, wm, wn, a_r, a_c8, b_r, b_c8, cacc);

    __nv_bfloat16* ph;
    __nv_bfloat16* pl;
    if (z == 2) { ph = g_vbh; pl = g_vbl; }
    else { ph = g_pjh + (size_t)z * (BH * S * HD); pl = g_pjl + (size_t)z * (BH * S * HD); }

#pragma unroll
    for (int mt = 0; mt < 2; mt++)
#pragma unroll
        for (int nt = 0; nt < 8; nt++) {
            int m = m0 + wm * 32 + mt * 16 + (lane >> 2);
            int n = n0 + wn * 64 + nt * 8 + (lane & 3) * 2;
            int bb = m >> 10, s = m & 1023, h = n >> 6, d = n & 63;
            size_t base = (((size_t)bb * H + h) * S + s) * HD + d;
            float b0 = bias[n], b1 = bias[n + 1];
            float x0 = cacc[mt][nt][0] + b0, x1 = cacc[mt][nt][1] + b1;
            float x2 = cacc[mt][nt][2] + b0, x3 = cacc[mt][nt][3] + b1;
            __nv_bfloat16 h0 = __float2bfloat16(x0), h1 = __float2bfloat16(x1);
            __nv_bfloat16 h2 = __float2bfloat16(x2), h3 = __float2bfloat16(x3);
            *(__nv_bfloat162*)(ph + base) = __halves2bfloat162(h0, h1);
            *(__nv_bfloat162*)(ph + base + 8 * HD) = __halves2bfloat162(h2, h3);
            *(__nv_bfloat162*)(pl + base) = __halves2bfloat162(
                __float2bfloat16(x0 - __bfloat162float(h0)),
                __float2bfloat16(x1 - __bfloat162float(h1)));
            *(__nv_bfloat162*)(pl + base + 8 * HD) = __halves2bfloat162(
                __float2bfloat16(x2 - __bfloat162float(h2)),
                __float2bfloat16(x3 - __bfloat162float(h3)));
        }
}

// ============================================================================
// GEMM kernel B: output projection -> d_out = AO @ Wo + bo
// ============================================================================
__global__ void __launch_bounds__(256, 2) gemm_out_tc(
    const float* __restrict__ bo, float* __restrict__ dout)
{
    extern __shared__ __align__(16) char smem[];
    uint32_t sb = smem_u32(smem);
    int m0 = blockIdx.y * 128, n0 = blockIdx.x * 128;
    const __nv_bfloat16* Bh = g_wth + (size_t)3 * E * E;
    const __nv_bfloat16* Bl = g_wtl + (size_t)3 * E * E;

    int lane = threadIdx.x & 31, wid = threadIdx.x >> 5;
    int wm = wid & 3, wn = wid >> 2;
    int a_r = lane & 15, a_c8 = (lane >> 4) * 8;
    int b_r = (lane & 7) | ((lane >> 4) << 3), b_c8 = ((lane >> 3) & 1) * 8;

    float cacc[2][8][4] = {};
    gemm_mainloop(sb, g_aoh, g_aol, Bh, Bl, m0, n0, wm, wn, a_r, a_c8, b_r, b_c8, cacc);

#pragma unroll
    for (int mt = 0; mt < 2; mt++)
#pragma unroll
        for (int nt = 0; nt < 8; nt++) {
            int m = m0 + wm * 32 + mt * 16 + (lane >> 2);
            int n = n0 + wn * 64 + nt * 8 + (lane & 3) * 2;
            float* op = dout + (size_t)m * E + n;
            float b0 = bo[n], b1 = bo[n + 1];
            *(float2*)op = make_float2(cacc[mt][nt][0] + b0, cacc[mt][nt][1] + b1);
            *(float2*)(op + 8 * E) = make_float2(cacc[mt][nt][2] + b0, cacc[mt][nt][3] + b1);
        }
}

// ============================================================================
// logits via mma (lower-tri tiles)
// ============================================================================
#define LPITCH 72
#define LTILE_B (128 * LPITCH * 2)   // 18432
#define LOG_SMEM (4 * LTILE_B)       // 73728

__global__ void __launch_bounds__(256, 2) logits_mma_kernel()
{
    extern __shared__ __align__(16) char smem[];
    uint32_t sb = smem_u32(smem);
    const int bh = blockIdx.y;
    int t = blockIdx.x, r = 0;
    while (t > r) { t -= r + 1; r++; }
    const int row0 = r * 128;
    const int col0 = t * 128;

    const __nv_bfloat16* Qh = g_pjh + (size_t)bh * S * HD;
    const __nv_bfloat16* Ql = g_pjl + (size_t)bh * S * HD;
    const __nv_bfloat16* Kh = g_pjh + (size_t)(BH + bh) * S * HD;
    const __nv_bfloat16* Kl = g_pjl + (size_t)(BH + bh) * S * HD;
    float* L = g_logits + (size_t)bh * S * S;

    int tid = threadIdx.x, lane = tid & 31, wid = tid >> 5;
    int wm = wid & 3, wn = wid >> 2;
    int a_r = lane & 15, a_c8 = (lane >> 4) * 8;
    int b_r = (lane & 7) | ((lane >> 4) << 3), b_c8 = ((lane >> 3) & 1) * 8;

#pragma unroll
    for (int i = 0; i < 4; i++) {
        int idx = tid + i * 256;
        int rr = idx >> 3, cc = (idx & 7) * 8;
        uint32_t so = (uint32_t)(rr * LPITCH + cc) * 2;
        cp16(sb + so,               Qh + (size_t)(row0 + rr) * HD + cc);
        cp16(sb + LTILE_B + so,     Ql + (size_t)(row0 + rr) * HD + cc);
        cp16(sb + 2 * LTILE_B + so, Kh + (size_t)(col0 + rr) * HD + cc);
        cp16(sb + 3 * LTILE_B + so, Kl + (size_t)(col0 + rr) * HD + cc);
    }
    asm volatile("cp.async.commit_group;" ::: "memory");
    asm volatile("cp.async.wait_group 0;" ::: "memory");
    __syncthreads();

    float cacc[2][8][4] = {};
#pragma unroll
    for (int kk = 0; kk < 64; kk += 16) {
        uint32_t ah[2][4], al[2][4], bhf[4][4], blf[4][4];
#pragma unroll
        for (int mt = 0; mt < 2; mt++) {
            uint32_t ro = (uint32_t)((wm * 32 + mt * 16 + a_r) * LPITCH + kk + a_c8) * 2;
            ldsm_x4(ah[mt], sb + ro);
            ldsm_x4(al[mt], sb + LTILE_B + ro);
        }
#pragma unroll
        for (int i = 0; i < 4; i++) {
            uint32_t ro = (uint32_t)((wn * 64 + i * 16 + b_r) * LPITCH + kk + b_c8) * 2;
            ldsm_x4(bhf[i], sb + 2 * LTILE_B + ro);
            ldsm_x4(blf[i], sb + 3 * LTILE_B + ro);
        }
#pragma unroll
        for (int mt = 0; mt < 2; mt++)
#pragma unroll
            for (int nt = 0; nt < 8; nt++) {
                const uint32_t* bp  = &bhf[nt >> 1][(nt & 1) * 2];
                const uint32_t* blp = &blf[nt >> 1][(nt & 1) * 2];
                mma_bf16(cacc[mt][nt], ah[mt], bp);
                mma_bf16(cacc[mt][nt], al[mt], bp);
                mma_bf16(cacc[mt][nt], ah[mt], blp);
            }
    }

    const float scale = 0.125f;
#pragma unroll
    for (int mt = 0; mt < 2; mt++)
#pragma unroll
        for (int nt = 0; nt < 8; nt++) {
            int m = row0 + wm * 32 + mt * 16 + (lane >> 2);
            int n = col0 + wn * 64 + nt * 8 + (lane & 3) * 2;
            float2 v0, v1;
            v0.x = (n     <= m) ? cacc[mt][nt][0] * scale : 0.f;
            v0.y = (n + 1 <= m) ? cacc[mt][nt][1] * scale : 0.f;
            v1.x = (n     <= m + 8) ? cacc[mt][nt][2] * scale : 0.f;
            v1.y = (n + 1 <= m + 8) ? cacc[mt][nt][3] * scale : 0.f;
            *(float2*)&L[(size_t)m * S + n] = v0;
            *(float2*)&L[(size_t)(m + 8) * S + n] = v1;
        }
}

// ============================================================================
// conv + softmax, HEAD-PAIR per block -> writes MIXED bf16 hi/lo splits
// ============================================================================
__device__ __forceinline__ void conv_load_row2(
    const float* __restrict__ L0, const float* __restrict__ L1, int qp, int c, int tid,
    float* sx0, float* sw0, float* sx1, float* sw1, float r0[6], float r1[6])
{
    float4 v0 = make_float4(0.f, 0.f, 0.f, 0.f);
    float4 v1 = v0;
    if (qp >= 0 && c <= qp) {
        v0 = *(const float4*)&L0[(size_t)qp * S + c];
        v1 = *(const float4*)&L1[(size_t)qp * S + c];
        if (c + 1 > qp) { v0.y = 0.f; v1.y = 0.f; }
        if (c + 2 > qp) { v0.z = 0.f; v1.z = 0.f; }
        if (c + 3 > qp) { v0.w = 0.f; v1.w = 0.f; }
    }
    __syncthreads();               // WAR: previous row's halo + ss reads done
    sx0[tid] = v0.x; sw0[tid] = v0.w;
    sx1[tid] = v1.x; sw1[tid] = v1.w;
    __syncthreads();
    r0[0] = (tid > 0) ? sw0[tid - 1] : 0.f;
    r0[1] = v0.x; r0[2] = v0.y; r0[3] = v0.z; r0[4] = v0.w;
    r0[5] = (tid < 255) ? sx0[tid + 1] : 0.f;
    r1[0] = (tid > 0) ? sw1[tid - 1] : 0.f;
    r1[1] = v1.x; r1[2] = v1.y; r1[3] = v1.z; r1[4] = v1.w;
    r1[5] = (tid < 255) ? sx1[tid + 1] : 0.f;
}

#define QROWS 8
__global__ __launch_bounds__(256) void conv_softmax_kernel(
    const float* __restrict__ kq_w, const float* __restrict__ kq_b,
    const float* __restrict__ mix_w)
{
    const int pb = blockIdx.y;               // pair index 0..15
    const int b = pb >> 3, hp = pb & 7;
    const int h0 = hp * 2, h1 = h0 + 1;
    const int bh0 = b * 16 + h0, bh1 = bh0 + 1;
    const int q0 = blockIdx.x * QROWS;
    const float* L0 = g_logits + (size_t)bh0 * S * S;
    const float* L1 = g_logits + (size_t)bh1 * S * S;

    __shared__ float sx0[256], sw0[256], sx1[256], sw1[256], ss0[8], ss1[8];
    const int tid = threadIdx.x;
    const int lane = tid & 31, wrp = tid >> 5;
    const int c = tid * 4;

    float wv0[9], wv1[9];
#pragma unroll
    for (int t = 0; t < 9; t++) { wv0[t] = kq_w[h0 * 9 + t]; wv1[t] = kq_w[h1 * 9 + t]; }
    const float bias0 = kq_b[h0], bias1 = kq_b[h1];
    const float eb0 = __expf(bias0), eb1 = __expf(bias1);
    const float m00 = mix_w[h0 * 2 + 0], m01 = mix_w[h0 * 2 + 1];
    const float m10 = mix_w[h1 * 2 + 0], m11 = mix_w[h1 * 2 + 1];

    float ra0[6], rb0[6], rc0[6], ra1[6], rb1[6], rc1[6];
    conv_load_row2(L0, L1, q0 - 2, c, tid, sx0, sw0, sx1, sw1, ra0, ra1);
    conv_load_row2(L0, L1, q0 - 1, c, tid, sx0, sw0, sx1, sw1, rb0, rb1);

    for (int i = 0; i < QROWS; i++) {
        const int q = q0 + i;
        conv_load_row2(L0, L1, q, c, tid, sx0, sw0, sx1, sw1, rc0, rc1);
        const int kmax = (q + 1 < S - 1) ? (q + 1) : (S - 1);

        float e0[4], e1[4];
        float es0 = 0.f, es1 = 0.f;
#pragma unroll
        for (int u = 0; u < 4; u++) {
            if (c + u <= kmax) {
                float c0 = wv0[0] * ra0[u] + wv0[1] * ra0[u + 1] + wv0[2] * ra0[u + 2]
                         + wv0[3] * rb0[u] + wv0[4] * rb0[u + 1] + wv0[5] * rb0[u + 2]
                         + wv0[6] * rc0[u] + wv0[7] * rc0[u + 1] + wv0[8] * rc0[u + 2] + bias0;
                float c1 = wv1[0] * ra1[u] + wv1[1] * ra1[u + 1] + wv1[2] * ra1[u + 2]
                         + wv1[3] * rb1[u] + wv1[4] * rb1[u + 1] + wv1[5] * rb1[u + 2]
                         + wv1[6] * rc1[u] + wv1[7] * rc1[u + 1] + wv1[8] * rc1[u + 2] + bias1;
                e0[u] = __expf(c0); es0 += e0[u];
                e1[u] = __expf(c1); es1 += e1[u];
            } else { e0[u] = 0.f; e1[u] = 0.f; }
        }
        float s0 = es0, s1 = es1;
#pragma unroll
        for (int o = 16; o; o >>= 1) {
            s0 += __shfl_xor_sync(0xffffffffu, s0, o);
            s1 += __shfl_xor_sync(0xffffffffu, s1, o);
        }
        if (lane == 0) { ss0[wrp] = s0; ss1[wrp] = s1; }
        __syncthreads();
        float t0 = ss0[lane & 7], t1 = ss1[lane & 7];
#pragma unroll
        for (int o = 4; o; o >>= 1) {
            t0 += __shfl_xor_sync(0xffffffffu, t0, o);
            t1 += __shfl_xor_sync(0xffffffffu, t1, o);
        }

        int cnt = S - 2 - q; if (cnt < 0) cnt = 0;
        float inv0 = 1.f / (t0 + (float)cnt * eb0);
        float inv1 = 1.f / (t1 + (float)cnt * eb1);
        float c0v = eb0 * inv0, c1v = eb1 * inv1;
        float cm0 = m00 * c0v + m01 * c1v;   // mixed const for output head h0
        float cm1 = m10 * c0v + m11 * c1v;   // mixed const for output head h1
        if (tid == 0) {
            g_rowconst[bh0 * S + q] = cm0;
            g_rowconst[bh1 * S + q] = cm1;
        }

        int Klim = ((q >> 6) << 6) + 128; if (Klim > S) Klim = S;
        if (c < Klim) {
            float a0[4], a1[4], x0[4], x1[4];
#pragma unroll
            for (int u = 0; u < 4; u++) {
                a0[u] = (c + u <= kmax) ? e0[u] * inv0 : c0v;
                a1[u] = (c + u <= kmax) ? e1[u] * inv1 : c1v;
                x0[u] = m00 * a0[u] + m01 * a1[u];
                x1[u] = m10 * a0[u] + m11 * a1[u];
            }
            size_t off0 = (size_t)bh0 * S * S + (size_t)q * S + c;
            size_t off1 = (size_t)bh1 * S * S + (size_t)q * S + c;
            split_store4g(g_mxh + off0, g_mxl + off0, x0);
            split_store4g(g_mxh + off1, g_mxl + off1, x1);
        }

#pragma unroll
        for (int u = 0; u < 6; u++) {
            ra0[u] = rb0[u]; rb0[u] = rc0[u];
            ra1[u] = rb1[u]; rb1[u] = rc1[u];
        }
    }
}

// ============================================================================
// V chunk sums (from bf16 hi/lo) + suffix scan
// ============================================================================
__global__ __launch_bounds__(256) void vchunk_kernel()
{
    const int bh = blockIdx.x, ci = blockIdx.y;
    const int tid = threadIdx.x;
    const int d = tid & 63, rg = tid >> 6;
    const __nv_bfloat16* Vh = g_vbh + (size_t)bh * S * HD;
    const __nv_bfloat16* Vl = g_vbl + (size_t)bh * S * HD;
    float s = 0.f;
#pragma unroll
    for (int r = 0; r < 16; r++) {
        size_t o = (size_t)(ci * 64 + rg * 16 + r) * HD + d;
        s += __bfloat162float(Vh[o]) + __bfloat162float(Vl[o]);
    }
    __shared__ float sm[4][64];
    sm[rg][d] = s;
    __syncthreads();
    if (tid < 64)
        g_suffV[((size_t)bh * 17 + ci) * HD + tid] = sm[0][tid] + sm[1][tid] + sm[2][tid] + sm[3][tid];
}

__global__ void vscan_kernel()
{
    const int bh = blockIdx.x, d = threadIdx.x;
    g_suffV[((size_t)bh * 17 + 16) * HD + d] = 0.f;
    float suf = 0.f;
    for (int ci = 15; ci >= 0; ci--) {
        suf += g_suffV[((size_t)bh * 17 + ci) * HD + d];
        g_suffV[((size_t)bh * 17 + ci) * HD + d] = suf;
    }
}

// ============================================================================
// pv via mma: A = pre-mixed bf16 splits (cp.async), B = V splits (trans ldsm)
// V loads use .ca (reused by all 16 q-tile blocks of a pair)
// ============================================================================
#define PV_APITCH 40
#define PV_VPITCH 136
#define PV_ATILE (64 * PV_APITCH * 2)          // 5120
#define PV_VTILE (32 * PV_VPITCH * 2)          // 8704
#define PV_STAGE (4 * PV_ATILE + 2 * PV_VTILE) // 37888
#define PV_SMEM (2 * PV_STAGE)                 // 75776

__device__ __forceinline__ void pv_load_stage(uint32_t sb, int stage,
    const __nv_bfloat16* __restrict__ A0h, const __nv_bfloat16* __restrict__ A0l,
    const __nv_bfloat16* __restrict__ A1h, const __nv_bfloat16* __restrict__ A1l,
    const __nv_bfloat16* __restrict__ V0h, const __nv_bfloat16* __restrict__ V0l,
    const __nv_bfloat16* __restrict__ V1h, const __nv_bfloat16* __restrict__ V1l,
    int k0)
{
    const int tid = threadIdx.x;
    uint32_t base = sb + stage * PV_STAGE;
    {
        int r = tid >> 2, ch = tid & 3;
        uint32_t so = (uint32_t)(r * PV_APITCH * 2 + ch * 16);
        size_t go = (size_t)r * S + k0 + ch * 8;
        cp16(base + so,                A0h + go);
        cp16(base + PV_ATILE + so,     A0l + go);
        cp16(base + 2 * PV_ATILE + so, A1h + go);
        cp16(base + 3 * PV_ATILE + so, A1l + go);
    }
    uint32_t vbase = base + 4 * PV_ATILE;
#pragma unroll
    for (int i = 0; i < 2; i++) {
        int idx = tid + i * 256;
        int r = idx >> 4, ch = idx & 15;
        uint32_t so = (uint32_t)(r * PV_VPITCH * 2 + ch * 16);
        size_t go = (size_t)(k0 + r) * HD;
        if (ch < 8) {
            cp16ca(vbase + so,            V0h + go + ch * 8);
            cp16ca(vbase + PV_VTILE + so, V0l + go + ch * 8);
        } else {
            cp16ca(vbase + so,            V1h + go + (ch - 8) * 8);
            cp16ca(vbase + PV_VTILE + so, V1l + go + (ch - 8) * 8);
        }
    }
}

__global__ void __launch_bounds__(256, 2) pv_mma_kernel(
    const float* __restrict__ mix_b,
    const float* __restrict__ dyt_alpha, const float* __restrict__ dyt_w,
    const float* __restrict__ dyt_b, const float* __restrict__ depth_scale)
{
    extern __shared__ __align__(16) char smem[];
    uint32_t sb = smem_u32(smem);
    const int pair = blockIdx.z;
    const int b = pair >> 3, hp = pair & 7;
    const int h0 = hp * 2, h1 = h0 + 1;
    const int bh0 = b * 16 + h0, bh1 = bh0 + 1;
    const int Q0 = (gridDim.y - 1 - blockIdx.y) * 64;
    int Klim = Q0 + 128; if (Klim > S) Klim = S;
    const int cidx = Klim >> 6;
    const int nch = Klim >> 5;

    const __nv_bfloat16* A0h = g_mxh + (size_t)bh0 * S * S + (size_t)Q0 * S;
    const __nv_bfloat16* A0l = g_mxl + (size_t)bh0 * S * S + (size_t)Q0 * S;
    const __nv_bfloat16* A1h = g_mxh + (size_t)bh1 * S * S + (size_t)Q0 * S;
    const __nv_bfloat16* A1l = g_mxl + (size_t)bh1 * S * S + (size_t)Q0 * S;
    const __nv_bfloat16* V0h = g_vbh + (size_t)bh0 * S * HD;
    const __nv_bfloat16* V0l = g_vbl + (size_t)bh0 * S * HD;
    const __nv_bfloat16* V1h = g_vbh + (size_t)bh1 * S * HD;
    const __nv_bfloat16* V1l = g_vbl + (size_t)bh1 * S * HD;

    const int tid = threadIdx.x, lane = tid & 31, wid = tid >> 5;
    const int wm = wid & 3, wn = wid >> 2;
    const int a_r = lane & 15, a_c8 = (lane >> 4) * 8;
    const int bt_r = lane & 15, bt_c8 = (lane >> 4) * 8;

    float acc[8][4] = {};

    pv_load_stage(sb, 0, A0h, A0l, A1h, A1l, V0h, V0l, V1h, V1l, 0);
    asm volatile("cp.async.commit_group;" ::: "memory");

    for (int c = 0; c < nch; c++) {
        if (c + 1 < nch) {
            pv_load_stage(sb, (c + 1) & 1, A0h, A0l, A1h, A1l, V0h, V0l, V1h, V1l, (c + 1) * 32);
            asm volatile("cp.async.commit_group;" ::: "memory");
            asm volatile("cp.async.wait_group 1;" ::: "memory");
        } else {
            asm volatile("cp.async.wait_group 0;" ::: "memory");
        }
        __syncthreads();
        uint32_t base = sb + (c & 1) * PV_STAGE;
        uint32_t sAh = base + (wn * 2) * PV_ATILE;
        uint32_t sAl = base + (wn * 2 + 1) * PV_ATILE;
        uint32_t sVh = base + 4 * PV_ATILE;
        uint32_t sVl = sVh + PV_VTILE;
#pragma unroll
        for (int kk = 0; kk < 32; kk += 16) {
            uint32_t ah[4], al[4];
            uint32_t ro = (uint32_t)((wm * 16 + a_r) * PV_APITCH + kk + a_c8) * 2;
            ldsm_x4(ah, sAh + ro);
            ldsm_x4(al, sAl + ro);
            uint32_t bhf[4][4], blf[4][4];
#pragma unroll
            for (int t = 0; t < 4; t++) {
                uint32_t vo = (uint32_t)((kk + bt_r) * PV_VPITCH + wn * 64 + t * 16 + bt_c8) * 2;
                ldsm_x4_t(bhf[t], sVh + vo);
                ldsm_x4_t(blf[t], sVl + vo);
            }
#pragma unroll
            for (int nt = 0; nt < 8; nt++) {
                const uint32_t* bp  = &bhf[nt >> 1][(nt & 1) * 2];
                const uint32_t* blp = &blf[nt >> 1][(nt & 1) * 2];
                mma_bf16(acc[nt], ah, bp);
                mma_bf16(acc[nt], al, bp);
                mma_bf16(acc[nt], ah, blp);
            }
        }
        __syncthreads();
    }

    const int bhh = wn ? bh1 : bh0;
    const float* suff = g_suffV + ((size_t)bhh * 17 + cidx) * HD;
    const float* csum = g_suffV + ((size_t)bhh * 17 + 0) * HD;
    const float* rcm = g_rowconst + bhh * S;
    const float mb = mix_b[wn ? h1 : h0];
    const float alpha = dyt_alpha[0], ds = depth_scale[0];
    const int q0r = Q0 + wm * 16 + (lane >> 2);
    const float cm0 = rcm[q0r];
    const float cm1 = rcm[q0r + 8];
    __nv_bfloat16* Oh = g_aoh + (size_t)b * S * E + h0 * HD;
    __nv_bfloat16* Ol = g_aol + (size_t)b * S * E + h0 * HD;

#pragma unroll
    for (int nt = 0; nt < 8; nt++) {
        int d = wn * 64 + nt * 8 + (lane & 3) * 2;
        int dl = d & 63;
        float sw0 = suff[dl], sw1 = suff[dl + 1];
        float cs0 = csum[dl], cs1 = csum[dl + 1];
        float w0 = dyt_w[dl], w1 = dyt_w[dl + 1];
        float bb0 = dyt_b[dl], bb1 = dyt_b[dl + 1];
#pragma unroll
        for (int half = 0; half < 2; half++) {
            int q = q0r + half * 8;
            float cm = half ? cm1 : cm0;
            float v0 = acc[nt][half * 2 + 0] + cm * sw0 + mb * cs0;
            float v1 = acc[nt][half * 2 + 1] + cm * sw1 + mb * cs1;
            v0 = (tanhf(alpha * v0) * w0 + bb0) * ds;
            v1 = (tanhf(alpha * v1) * w1 + bb1) * ds;
            __nv_bfloat16 h0v = __float2bfloat16(v0), h1v = __float2bfloat16(v1);
            *(__nv_bfloat162*)&Oh[(size_t)q * E + d] = __halves2bfloat162(h0v, h1v);
            *(__nv_bfloat162*)&Ol[(size_t)q * E + d] = __halves2bfloat162(
                __float2bfloat16(v0 - __bfloat162float(h0v)),
                __float2bfloat16(v1 - __bfloat162float(h1v)));
        }
    }
}

// ============================================================================
// Launch  (R13 champion configuration)
// ============================================================================
extern "C" void kernel_launch(void* const* d_in, const int* in_sizes, int n_in,
                              void* d_out, int out_size)
{
    const float* Q   = (const float*)d_in[0];
    const float* K   = (const float*)d_in[1];
    const float* V   = (const float*)d_in[2];
    const float* Wq  = (const float*)d_in[3];
    const float* bq  = (const float*)d_in[4];
    const float* Wk  = (const float*)d_in[5];
    const float* bk  = (const float*)d_in[6];
    const float* Wv  = (const float*)d_in[7];
    const float* bv  = (const float*)d_in[8];
    const float* Wo  = (const float*)d_in[9];
    const float* bo  = (const float*)d_in[10];
    const float* kq_w = (const float*)d_in[11];
    const float* kq_b = (const float*)d_in[12];
    const float* mix_w = (const float*)d_in[13];
    const float* mix_b = (const float*)d_in[14];
    const float* dyt_alpha = (const float*)d_in[15];
    const float* dyt_w = (const float*)d_in[16];
    const float* dyt_b = (const float*)d_in[17];
    const float* depth_scale = (const float*)d_in[18];

    cudaFuncSetAttribute(gemm_qkv_tc, cudaFuncAttributeMaxDynamicSharedMemorySize, GEMM_SMEM);
    cudaFuncSetAttribute(gemm_out_tc, cudaFuncAttributeMaxDynamicSharedMemorySize, GEMM_SMEM);
    cudaFuncSetAttribute(logits_mma_kernel, cudaFuncAttributeMaxDynamicSharedMemorySize, LOG_SMEM);
    cudaFuncSetAttribute(pv_mma_kernel, cudaFuncAttributeMaxDynamicSharedMemorySize, PV_SMEM);

    asplit_kernel<<<dim3(2048, 1, 3), 256>>>(Q, K, V);
    wsplit_kernel<<<dim3(32, 32, 4), dim3(32, 8)>>>(Wq, Wk, Wv, Wo);
    gemm_qkv_tc<<<dim3(8, 16, 3), 256, GEMM_SMEM>>>(bq, bk, bv);
    vchunk_kernel<<<dim3(BH, 16), 256>>>();
    vscan_kernel<<<BH, 64>>>();
    logits_mma_kernel<<<dim3(36, BH), 256, LOG_SMEM>>>();
    conv_softmax_kernel<<<dim3(S / QROWS, BH / 2), 256>>>(kq_w, kq_b, mix_w);
    pv_mma_kernel<<<dim3(1, S / 64, BH / 2), 256, PV_SMEM>>>(mix_b, dyt_alpha, dyt_w, dyt_b, depth_scale);
    gemm_out_tc<<<dim3(8, 16), 256, GEMM_SMEM>>>(bo, (float*)d_out);
}

// round 17
// speedup vs baseline: 1.5639x; 1.0081x over previous
#include <cuda_runtime.h>
#include <cuda_bf16.h>
#include <math.h>
#include <cstdint>

#define S 1024
#define E 1024
#define H 16
#define HD 64
#define BATCH 2
#define BH (BATCH * H)     // 32
#define M_TOT (BATCH * S)  // 2048

// ---------------- scratch (device globals; no runtime allocation) ----------
__device__ __align__(16) float g_logits[BH * S * S];
__device__ __align__(16) float g_rowconst[BH * S];          // MIXED row consts
__device__ __align__(16) float g_suffV[BH * 17 * HD];
__device__ __align__(16) __nv_bfloat16 g_mxh[BH * S * S];   // mixed attn hi
__device__ __align__(16) __nv_bfloat16 g_mxl[BH * S * S];   // mixed attn lo
__device__ __align__(16) __nv_bfloat16 g_ah[3 * M_TOT * E];
__device__ __align__(16) __nv_bfloat16 g_al[3 * M_TOT * E];
__device__ __align__(16) __nv_bfloat16 g_wth[4 * E * E];   // W^T [n][k]
__device__ __align__(16) __nv_bfloat16 g_wtl[4 * E * E];
__device__ __align__(16) __nv_bfloat16 g_aoh[M_TOT * E];
__device__ __align__(16) __nv_bfloat16 g_aol[M_TOT * E];
__device__ __align__(16) __nv_bfloat16 g_pjh[2 * BH * S * HD];  // q,k hi
__device__ __align__(16) __nv_bfloat16 g_pjl[2 * BH * S * HD];  // q,k lo
__device__ __align__(16) __nv_bfloat16 g_vbh[BH * S * HD];      // V hi
__device__ __align__(16) __nv_bfloat16 g_vbl[BH * S * HD];      // V lo

// ============================ PTX helpers ===================================
__device__ __forceinline__ uint32_t smem_u32(const void* p) {
    uint32_t a;
    asm("{ .reg .u64 t; cvta.to.shared.u64 t, %1; cvt.u32.u64 %0, t; }" : "=r"(a) : "l"(p));
    return a;
}
__device__ __forceinline__ void ldsm_x4(uint32_t* r, uint32_t addr) {
    asm volatile("ldmatrix.sync.aligned.m8n8.x4.shared.b16 {%0,%1,%2,%3}, [%4];"
        : "=r"(r[0]), "=r"(r[1]), "=r"(r[2]), "=r"(r[3]) : "r"(addr));
}
__device__ __forceinline__ void ldsm_x4_t(uint32_t* r, uint32_t addr) {
    asm volatile("ldmatrix.sync.aligned.m8n8.x4.trans.shared.b16 {%0,%1,%2,%3}, [%4];"
        : "=r"(r[0]), "=r"(r[1]), "=r"(r[2]), "=r"(r[3]) : "r"(addr));
}
__device__ __forceinline__ void mma_bf16(float* c, const uint32_t* a, const uint32_t* b) {
    asm volatile("mma.sync.aligned.m16n8k16.row.col.f32.bf16.bf16.f32 "
        "{%0,%1,%2,%3}, {%4,%5,%6,%7}, {%8,%9}, {%0,%1,%2,%3};"
        : "+f"(c[0]), "+f"(c[1]), "+f"(c[2]), "+f"(c[3])
        : "r"(a[0]), "r"(a[1]), "r"(a[2]), "r"(a[3]), "r"(b[0]), "r"(b[1]));
}
__device__ __forceinline__ void cp16(uint32_t saddr, const void* g) {
    asm volatile("cp.async.cg.shared.global [%0], [%1], 16;" :: "r"(saddr), "l"(g));
}
__device__ __forceinline__ void cp16ca(uint32_t saddr, const void* g) {
    asm volatile("cp.async.ca.shared.global [%0], [%1], 16;" :: "r"(saddr), "l"(g));
}
// split f32x4 -> one 8B hi store + one 8B lo store (gmem)
__device__ __forceinline__ void split_store4g(__nv_bfloat16* hp, __nv_bfloat16* lp, const float* x) {
    __nv_bfloat16 h0 = __float2bfloat16(x[0]), h1 = __float2bfloat16(x[1]);
    __nv_bfloat16 h2 = __float2bfloat16(x[2]), h3 = __float2bfloat16(x[3]);
    __nv_bfloat162 a = __halves2bfloat162(h0, h1), b = __halves2bfloat162(h2, h3);
    uint2 hv; hv.x = *(uint32_t*)&a; hv.y = *(uint32_t*)&b;
    *(uint2*)hp = hv;
    __nv_bfloat162 c = __halves2bfloat162(
        __float2bfloat16(x[0] - __bfloat162float(h0)),
        __float2bfloat16(x[1] - __bfloat162float(h1)));
    __nv_bfloat162 d = __halves2bfloat162(
        __float2bfloat16(x[2] - __bfloat162float(h2)),
        __float2bfloat16(x[3] - __bfloat162float(h3)));
    uint2 lv; lv.x = *(uint32_t*)&c; lv.y = *(uint32_t*)&d;
    *(uint2*)lp = lv;
}

// GEMM geometry: 128x128 block, BK=32, 8 warps (4m x 2n), warp 32x64.
#define PITCH 40                 // bf16 per smem row (80 B: conflict-free ldmatrix)
#define TILE_B 10240             // 128 * PITCH * 2
#define STAGE_B 40960            // 4 tiles (Ah, Al, Bh, Bl)
#define GEMM_SMEM (2 * STAGE_B)  // 81920

// ============================================================================
// prep: split f32 -> bf16 hi/lo (Q, K, V inputs)
// ============================================================================
__global__ __launch_bounds__(256) void asplit_kernel(
    const float* __restrict__ Q, const float* __restrict__ K, const float* __restrict__ V)
{
    int z = blockIdx.z;
    const float* X = (z == 0) ? Q : (z == 1) ? K : V;
    __nv_bfloat16* hp = g_ah + (size_t)z * M_TOT * E;
    __nv_bfloat16* lp = g_al + (size_t)z * M_TOT * E;
    int i = (blockIdx.x * 256 + threadIdx.x) * 4;
    float4 v = *(const float4*)(X + i);
    float vv[4] = {v.x, v.y, v.z, v.w};
#pragma unroll
    for (int j = 0; j < 4; j++) {
        __nv_bfloat16 h = __float2bfloat16(vv[j]);
        hp[i + j] = h;
        lp[i + j] = __float2bfloat16(vv[j] - __bfloat162float(h));
    }
}

// ============================================================================
// prep: transpose + split weights: Wt[n][k] = W[k][n], bf16 hi/lo
// ============================================================================
__global__ void wsplit_kernel(const float* __restrict__ Wq, const float* __restrict__ Wk,
                              const float* __restrict__ Wv, const float* __restrict__ Wo)
{
    int z = blockIdx.z;
    const float* W = (z == 0) ? Wq : (z == 1) ? Wk : (z == 2) ? Wv : Wo;
    __nv_bfloat16* th = g_wth + (size_t)z * E * E;
    __nv_bfloat16* tl = g_wtl + (size_t)z * E * E;
    __shared__ float tile[32][33];
    int n0 = blockIdx.x * 32, k0 = blockIdx.y * 32;
    int tx = threadIdx.x, ty = threadIdx.y;
    for (int i = ty; i < 32; i += 8)
        tile[i][tx] = W[(size_t)(k0 + i) * E + n0 + tx];
    __syncthreads();
    for (int i = ty; i < 32; i += 8) {
        float v = tile[tx][i];
        __nv_bfloat16 h = __float2bfloat16(v);
        th[(size_t)(n0 + i) * E + k0 + tx] = h;
        tl[(size_t)(n0 + i) * E + k0 + tx] = __float2bfloat16(v - __bfloat162float(h));
    }
}

// ============================================================================
// mma.sync GEMM core (E-deep, pipelined); both operands .ca (8x block reuse)
// ============================================================================
__device__ __forceinline__ void gemm_load_stage(uint32_t sbs,
    const __nv_bfloat16* __restrict__ Ah, const __nv_bfloat16* __restrict__ Al,
    const __nv_bfloat16* __restrict__ Bh, const __nv_bfloat16* __restrict__ Bl,
    int m0, int n0, int k0)
{
    int t = threadIdx.x;
#pragma unroll
    for (int i = 0; i < 2; i++) {
        int idx = t + i * 256;
        int r = idx >> 2, c = (idx & 3) * 8;
        uint32_t so = (uint32_t)(r * PITCH + c) * 2;
        cp16ca(sbs + so,              Ah + (size_t)(m0 + r) * E + k0 + c);
        cp16ca(sbs + TILE_B + so,     Al + (size_t)(m0 + r) * E + k0 + c);
        cp16ca(sbs + 2 * TILE_B + so, Bh + (size_t)(n0 + r) * E + k0 + c);
        cp16ca(sbs + 3 * TILE_B + so, Bl + (size_t)(n0 + r) * E + k0 + c);
    }
}

__device__ __forceinline__ void gemm_compute_stage(
    uint32_t sb, int wm, int wn, int a_r, int a_c8, int b_r, int b_c8,
    float cacc[2][8][4])
{
#pragma unroll
    for (int kk = 0; kk < 32; kk += 16) {
        uint32_t ah[2][4], al[2][4], bh[4][4], bl[4][4];
#pragma unroll
        for (int mt = 0; mt < 2; mt++) {
            uint32_t ro = (uint32_t)((wm * 32 + mt * 16 + a_r) * PITCH + kk + a_c8) * 2;
            ldsm_x4(ah[mt], sb + ro);
            ldsm_x4(al[mt], sb + TILE_B + ro);
        }
#pragma unroll
        for (int i = 0; i < 4; i++) {
            uint32_t ro = (uint32_t)((wn * 64 + i * 16 + b_r) * PITCH + kk + b_c8) * 2;
            ldsm_x4(bh[i], sb + 2 * TILE_B + ro);
            ldsm_x4(bl[i], sb + 3 * TILE_B + ro);
        }
#pragma unroll
        for (int mt = 0; mt < 2; mt++)
#pragma unroll
            for (int nt = 0; nt < 8; nt++) {
                const uint32_t* bp  = &bh[nt >> 1][(nt & 1) * 2];
                const uint32_t* blp = &bl[nt >> 1][(nt & 1) * 2];
                mma_bf16(cacc[mt][nt], ah[mt], bp);
                mma_bf16(cacc[mt][nt], al[mt], bp);
                mma_bf16(cacc[mt][nt], ah[mt], blp);
            }
    }
}

__device__ __forceinline__ void gemm_mainloop(uint32_t sb,
    const __nv_bfloat16* Ah, const __nv_bfloat16* Al,
    const __nv_bfloat16* Bh, const __nv_bfloat16* Bl,
    int m0, int n0, int wm, int wn, int a_r, int a_c8, int b_r, int b_c8,
    float cacc[2][8][4])
{
    gemm_load_stage(sb, Ah, Al, Bh, Bl, m0, n0, 0);
    asm volatile("cp.async.commit_group;" ::: "memory");
    for (int c = 0; c < 32; c++) {
        if (c + 1 < 32) {
            gemm_load_stage(sb + ((c + 1) & 1) * STAGE_B, Ah, Al, Bh, Bl, m0, n0, (c + 1) * 32);
            asm volatile("cp.async.commit_group;" ::: "memory");
            asm volatile("cp.async.wait_group 1;" ::: "memory");
        } else {
            asm volatile("cp.async.wait_group 0;" ::: "memory");
        }
        __syncthreads();
        gemm_compute_stage(sb + (c & 1) * STAGE_B, wm, wn, a_r, a_c8, b_r, b_c8, cacc);
        __syncthreads();
    }
}

// ============================================================================
// GEMM kernel A: QKV projections. z<2 -> q/k bf16 splits; z==2 -> V bf16 splits
// ============================================================================
__global__ void __launch_bounds__(256, 2) gemm_qkv_tc(
    const float* __restrict__ bq, const float* __restrict__ bk, const float* __restrict__ bv)
{
    extern __shared__ __align__(16) char smem[];
    uint32_t sb = smem_u32(smem);
    int z = blockIdx.z;
    int m0 = blockIdx.y * 128, n0 = blockIdx.x * 128;
    const __nv_bfloat16* Ah = g_ah + (size_t)z * M_TOT * E;
    const __nv_bfloat16* Al = g_al + (size_t)z * M_TOT * E;
    const __nv_bfloat16* Bh = g_wth + (size_t)z * E * E;
    const __nv_bfloat16* Bl = g_wtl + (size_t)z * E * E;
    const float* bias = (z == 0) ? bq : (z == 1) ? bk : bv;

    int lane = threadIdx.x & 31, wid = threadIdx.x >> 5;
    int wm = wid & 3, wn = wid >> 2;
    int a_r = lane & 15, a_c8 = (lane >> 4) * 8;
    int b_r = (lane & 7) | ((lane >> 4) << 3), b_c8 = ((lane >> 3) & 1) * 8;

    float cacc[2][8][4] = {};
    gemm_mainloop(sb, Ah, Al, Bh, Bl, m0, n0, wm, wn, a_r, a_c8, b_r, b_c8, cacc);

    __nv_bfloat16* ph;
    __nv_bfloat16* pl;
    if (z == 2) { ph = g_vbh; pl = g_vbl; }
    else { ph = g_pjh + (size_t)z * (BH * S * HD); pl = g_pjl + (size_t)z * (BH * S * HD); }

#pragma unroll
    for (int mt = 0; mt < 2; mt++)
#pragma unroll
        for (int nt = 0; nt < 8; nt++) {
            int m = m0 + wm * 32 + mt * 16 + (lane >> 2);
            int n = n0 + wn * 64 + nt * 8 + (lane & 3) * 2;
            int bb = m >> 10, s = m & 1023, h = n >> 6, d = n & 63;
            size_t base = (((size_t)bb * H + h) * S + s) * HD + d;
            float b0 = bias[n], b1 = bias[n + 1];
            float x0 = cacc[mt][nt][0] + b0, x1 = cacc[mt][nt][1] + b1;
            float x2 = cacc[mt][nt][2] + b0, x3 = cacc[mt][nt][3] + b1;
            __nv_bfloat16 h0 = __float2bfloat16(x0), h1 = __float2bfloat16(x1);
            __nv_bfloat16 h2 = __float2bfloat16(x2), h3 = __float2bfloat16(x3);
            *(__nv_bfloat162*)(ph + base) = __halves2bfloat162(h0, h1);
            *(__nv_bfloat162*)(ph + base + 8 * HD) = __halves2bfloat162(h2, h3);
            *(__nv_bfloat162*)(pl + base) = __halves2bfloat162(
                __float2bfloat16(x0 - __bfloat162float(h0)),
                __float2bfloat16(x1 - __bfloat162float(h1)));
            *(__nv_bfloat162*)(pl + base + 8 * HD) = __halves2bfloat162(
                __float2bfloat16(x2 - __bfloat162float(h2)),
                __float2bfloat16(x3 - __bfloat162float(h3)));
        }
}

// ============================================================================
// GEMM kernel B: output projection -> d_out = AO @ Wo + bo
// ============================================================================
__global__ void __launch_bounds__(256, 2) gemm_out_tc(
    const float* __restrict__ bo, float* __restrict__ dout)
{
    extern __shared__ __align__(16) char smem[];
    uint32_t sb = smem_u32(smem);
    int m0 = blockIdx.y * 128, n0 = blockIdx.x * 128;
    const __nv_bfloat16* Bh = g_wth + (size_t)3 * E * E;
    const __nv_bfloat16* Bl = g_wtl + (size_t)3 * E * E;

    int lane = threadIdx.x & 31, wid = threadIdx.x >> 5;
    int wm = wid & 3, wn = wid >> 2;
    int a_r = lane & 15, a_c8 = (lane >> 4) * 8;
    int b_r = (lane & 7) | ((lane >> 4) << 3), b_c8 = ((lane >> 3) & 1) * 8;

    float cacc[2][8][4] = {};
    gemm_mainloop(sb, g_aoh, g_aol, Bh, Bl, m0, n0, wm, wn, a_r, a_c8, b_r, b_c8, cacc);

#pragma unroll
    for (int mt = 0; mt < 2; mt++)
#pragma unroll
        for (int nt = 0; nt < 8; nt++) {
            int m = m0 + wm * 32 + mt * 16 + (lane >> 2);
            int n = n0 + wn * 64 + nt * 8 + (lane & 3) * 2;
            float* op = dout + (size_t)m * E + n;
            float b0 = bo[n], b1 = bo[n + 1];
            *(float2*)op = make_float2(cacc[mt][nt][0] + b0, cacc[mt][nt][1] + b1);
            *(float2*)(op + 8 * E) = make_float2(cacc[mt][nt][2] + b0, cacc[mt][nt][3] + b1);
        }
}

// ============================================================================
// logits via mma (lower-tri tiles)
// ============================================================================
#define LPITCH 72
#define LTILE_B (128 * LPITCH * 2)   // 18432
#define LOG_SMEM (4 * LTILE_B)       // 73728

__global__ void __launch_bounds__(256, 2) logits_mma_kernel()
{
    extern __shared__ __align__(16) char smem[];
    uint32_t sb = smem_u32(smem);
    const int bh = blockIdx.y;
    int t = blockIdx.x, r = 0;
    while (t > r) { t -= r + 1; r++; }
    const int row0 = r * 128;
    const int col0 = t * 128;

    const __nv_bfloat16* Qh = g_pjh + (size_t)bh * S * HD;
    const __nv_bfloat16* Ql = g_pjl + (size_t)bh * S * HD;
    const __nv_bfloat16* Kh = g_pjh + (size_t)(BH + bh) * S * HD;
    const __nv_bfloat16* Kl = g_pjl + (size_t)(BH + bh) * S * HD;
    float* L = g_logits + (size_t)bh * S * S;

    int tid = threadIdx.x, lane = tid & 31, wid = tid >> 5;
    int wm = wid & 3, wn = wid >> 2;
    int a_r = lane & 15, a_c8 = (lane >> 4) * 8;
    int b_r = (lane & 7) | ((lane >> 4) << 3), b_c8 = ((lane >> 3) & 1) * 8;

#pragma unroll
    for (int i = 0; i < 4; i++) {
        int idx = tid + i * 256;
        int rr = idx >> 3, cc = (idx & 7) * 8;
        uint32_t so = (uint32_t)(rr * LPITCH + cc) * 2;
        cp16(sb + so,               Qh + (size_t)(row0 + rr) * HD + cc);
        cp16(sb + LTILE_B + so,     Ql + (size_t)(row0 + rr) * HD + cc);
        cp16(sb + 2 * LTILE_B + so, Kh + (size_t)(col0 + rr) * HD + cc);
        cp16(sb + 3 * LTILE_B + so, Kl + (size_t)(col0 + rr) * HD + cc);
    }
    asm volatile("cp.async.commit_group;" ::: "memory");
    asm volatile("cp.async.wait_group 0;" ::: "memory");
    __syncthreads();

    float cacc[2][8][4] = {};
#pragma unroll
    for (int kk = 0; kk < 64; kk += 16) {
        uint32_t ah[2][4], al[2][4], bhf[4][4], blf[4][4];
#pragma unroll
        for (int mt = 0; mt < 2; mt++) {
            uint32_t ro = (uint32_t)((wm * 32 + mt * 16 + a_r) * LPITCH + kk + a_c8) * 2;
            ldsm_x4(ah[mt], sb + ro);
            ldsm_x4(al[mt], sb + LTILE_B + ro);
        }
#pragma unroll
        for (int i = 0; i < 4; i++) {
            uint32_t ro = (uint32_t)((wn * 64 + i * 16 + b_r) * LPITCH + kk + b_c8) * 2;
            ldsm_x4(bhf[i], sb + 2 * LTILE_B + ro);
            ldsm_x4(blf[i], sb + 3 * LTILE_B + ro);
        }
#pragma unroll
        for (int mt = 0; mt < 2; mt++)
#pragma unroll
            for (int nt = 0; nt < 8; nt++) {
                const uint32_t* bp  = &bhf[nt >> 1][(nt & 1) * 2];
                const uint32_t* blp = &blf[nt >> 1][(nt & 1) * 2];
                mma_bf16(cacc[mt][nt], ah[mt], bp);
                mma_bf16(cacc[mt][nt], al[mt], bp);
                mma_bf16(cacc[mt][nt], ah[mt], blp);
            }
    }

    const float scale = 0.125f;
#pragma unroll
    for (int mt = 0; mt < 2; mt++)
#pragma unroll
        for (int nt = 0; nt < 8; nt++) {
            int m = row0 + wm * 32 + mt * 16 + (lane >> 2);
            int n = col0 + wn * 64 + nt * 8 + (lane & 3) * 2;
            float2 v0, v1;
            v0.x = (n     <= m) ? cacc[mt][nt][0] * scale : 0.f;
            v0.y = (n + 1 <= m) ? cacc[mt][nt][1] * scale : 0.f;
            v1.x = (n     <= m + 8) ? cacc[mt][nt][2] * scale : 0.f;
            v1.y = (n + 1 <= m + 8) ? cacc[mt][nt][3] * scale : 0.f;
            *(float2*)&L[(size_t)m * S + n] = v0;
            *(float2*)&L[(size_t)(m + 8) * S + n] = v1;
        }
}

// ============================================================================
// conv + softmax, HEAD-PAIR per block -> writes MIXED bf16 hi/lo splits
// ============================================================================
__device__ __forceinline__ void conv_load_row2(
    const float* __restrict__ L0, const float* __restrict__ L1, int qp, int c, int tid,
    float* sx0, float* sw0, float* sx1, float* sw1, float r0[6], float r1[6])
{
    float4 v0 = make_float4(0.f, 0.f, 0.f, 0.f);
    float4 v1 = v0;
    if (qp >= 0 && c <= qp) {
        v0 = *(const float4*)&L0[(size_t)qp * S + c];
        v1 = *(const float4*)&L1[(size_t)qp * S + c];
        if (c + 1 > qp) { v0.y = 0.f; v1.y = 0.f; }
        if (c + 2 > qp) { v0.z = 0.f; v1.z = 0.f; }
        if (c + 3 > qp) { v0.w = 0.f; v1.w = 0.f; }
    }
    __syncthreads();               // WAR: previous row's halo + ss reads done
    sx0[tid] = v0.x; sw0[tid] = v0.w;
    sx1[tid] = v1.x; sw1[tid] = v1.w;
    __syncthreads();
    r0[0] = (tid > 0) ? sw0[tid - 1] : 0.f;
    r0[1] = v0.x; r0[2] = v0.y; r0[3] = v0.z; r0[4] = v0.w;
    r0[5] = (tid < 255) ? sx0[tid + 1] : 0.f;
    r1[0] = (tid > 0) ? sw1[tid - 1] : 0.f;
    r1[1] = v1.x; r1[2] = v1.y; r1[3] = v1.z; r1[4] = v1.w;
    r1[5] = (tid < 255) ? sx1[tid + 1] : 0.f;
}

#define QROWS 8
__global__ __launch_bounds__(256) void conv_softmax_kernel(
    const float* __restrict__ kq_w, const float* __restrict__ kq_b,
    const float* __restrict__ mix_w)
{
    const int pb = blockIdx.y;               // pair index 0..15
    const int b = pb >> 3, hp = pb & 7;
    const int h0 = hp * 2, h1 = h0 + 1;
    const int bh0 = b * 16 + h0, bh1 = bh0 + 1;
    const int q0 = blockIdx.x * QROWS;
    const float* L0 = g_logits + (size_t)bh0 * S * S;
    const float* L1 = g_logits + (size_t)bh1 * S * S;

    __shared__ float sx0[256], sw0[256], sx1[256], sw1[256], ss0[8], ss1[8];
    const int tid = threadIdx.x;
    const int lane = tid & 31, wrp = tid >> 5;
    const int c = tid * 4;

    float wv0[9], wv1[9];
#pragma unroll
    for (int t = 0; t < 9; t++) { wv0[t] = kq_w[h0 * 9 + t]; wv1[t] = kq_w[h1 * 9 + t]; }
    const float bias0 = kq_b[h0], bias1 = kq_b[h1];
    const float eb0 = __expf(bias0), eb1 = __expf(bias1);
    const float m00 = mix_w[h0 * 2 + 0], m01 = mix_w[h0 * 2 + 1];
    const float m10 = mix_w[h1 * 2 + 0], m11 = mix_w[h1 * 2 + 1];

    float ra0[6], rb0[6], rc0[6], ra1[6], rb1[6], rc1[6];
    conv_load_row2(L0, L1, q0 - 2, c, tid, sx0, sw0, sx1, sw1, ra0, ra1);
    conv_load_row2(L0, L1, q0 - 1, c, tid, sx0, sw0, sx1, sw1, rb0, rb1);

    for (int i = 0; i < QROWS; i++) {
        const int q = q0 + i;
        conv_load_row2(L0, L1, q, c, tid, sx0, sw0, sx1, sw1, rc0, rc1);
        const int kmax = (q + 1 < S - 1) ? (q + 1) : (S - 1);

        float e0[4], e1[4];
        float es0 = 0.f, es1 = 0.f;
#pragma unroll
        for (int u = 0; u < 4; u++) {
            if (c + u <= kmax) {
                float c0 = wv0[0] * ra0[u] + wv0[1] * ra0[u + 1] + wv0[2] * ra0[u + 2]
                         + wv0[3] * rb0[u] + wv0[4] * rb0[u + 1] + wv0[5] * rb0[u + 2]
                         + wv0[6] * rc0[u] + wv0[7] * rc0[u + 1] + wv0[8] * rc0[u + 2] + bias0;
                float c1 = wv1[0] * ra1[u] + wv1[1] * ra1[u + 1] + wv1[2] * ra1[u + 2]
                         + wv1[3] * rb1[u] + wv1[4] * rb1[u + 1] + wv1[5] * rb1[u + 2]
                         + wv1[6] * rc1[u] + wv1[7] * rc1[u + 1] + wv1[8] * rc1[u + 2] + bias1;
                e0[u] = __expf(c0); es0 += e0[u];
                e1[u] = __expf(c1); es1 += e1[u];
            } else { e0[u] = 0.f; e1[u] = 0.f; }
        }
        float s0 = es0, s1 = es1;
#pragma unroll
        for (int o = 16; o; o >>= 1) {
            s0 += __shfl_xor_sync(0xffffffffu, s0, o);
            s1 += __shfl_xor_sync(0xffffffffu, s1, o);
        }
        if (lane == 0) { ss0[wrp] = s0; ss1[wrp] = s1; }
        __syncthreads();
        float t0 = ss0[lane & 7], t1 = ss1[lane & 7];
#pragma unroll
        for (int o = 4; o; o >>= 1) {
            t0 += __shfl_xor_sync(0xffffffffu, t0, o);
            t1 += __shfl_xor_sync(0xffffffffu, t1, o);
        }

        int cnt = S - 2 - q; if (cnt < 0) cnt = 0;
        float inv0 = 1.f / (t0 + (float)cnt * eb0);
        float inv1 = 1.f / (t1 + (float)cnt * eb1);
        float c0v = eb0 * inv0, c1v = eb1 * inv1;
        float cm0 = m00 * c0v + m01 * c1v;   // mixed const for output head h0
        float cm1 = m10 * c0v + m11 * c1v;   // mixed const for output head h1
        if (tid == 0) {
            g_rowconst[bh0 * S + q] = cm0;
            g_rowconst[bh1 * S + q] = cm1;
        }

        int Klim = ((q >> 6) << 6) + 128; if (Klim > S) Klim = S;
        if (c < Klim) {
            float a0[4], a1[4], x0[4], x1[4];
#pragma unroll
            for (int u = 0; u < 4; u++) {
                a0[u] = (c + u <= kmax) ? e0[u] * inv0 : c0v;
                a1[u] = (c + u <= kmax) ? e1[u] * inv1 : c1v;
                x0[u] = m00 * a0[u] + m01 * a1[u];
                x1[u] = m10 * a0[u] + m11 * a1[u];
            }
            size_t off0 = (size_t)bh0 * S * S + (size_t)q * S + c;
            size_t off1 = (size_t)bh1 * S * S + (size_t)q * S + c;
            split_store4g(g_mxh + off0, g_mxl + off0, x0);
            split_store4g(g_mxh + off1, g_mxl + off1, x1);
        }

#pragma unroll
        for (int u = 0; u < 6; u++) {
            ra0[u] = rb0[u]; rb0[u] = rc0[u];
            ra1[u] = rb1[u]; rb1[u] = rc1[u];
        }
    }
}

// ============================================================================
// V chunk sums (from bf16 hi/lo) + suffix scan
// ============================================================================
__global__ __launch_bounds__(256) void vchunk_kernel()
{
    const int bh = blockIdx.x, ci = blockIdx.y;
    const int tid = threadIdx.x;
    const int d = tid & 63, rg = tid >> 6;
    const __nv_bfloat16* Vh = g_vbh + (size_t)bh * S * HD;
    const __nv_bfloat16* Vl = g_vbl + (size_t)bh * S * HD;
    float s = 0.f;
#pragma unroll
    for (int r = 0; r < 16; r++) {
        size_t o = (size_t)(ci * 64 + rg * 16 + r) * HD + d;
        s += __bfloat162float(Vh[o]) + __bfloat162float(Vl[o]);
    }
    __shared__ float sm[4][64];
    sm[rg][d] = s;
    __syncthreads();
    if (tid < 64)
        g_suffV[((size_t)bh * 17 + ci) * HD + tid] = sm[0][tid] + sm[1][tid] + sm[2][tid] + sm[3][tid];
}

__global__ void vscan_kernel()
{
    const int bh = blockIdx.x, d = threadIdx.x;
    g_suffV[((size_t)bh * 17 + 16) * HD + d] = 0.f;
    float suf = 0.f;
    for (int ci = 15; ci >= 0; ci--) {
        suf += g_suffV[((size_t)bh * 17 + ci) * HD + d];
        g_suffV[((size_t)bh * 17 + ci) * HD + d] = suf;
    }
}

// ============================================================================
// pv via mma: A = pre-mixed bf16 splits (cp.async), B = V splits (trans ldsm)
// V loads use .ca (reused by all 16 q-tile blocks of a pair)
// ============================================================================
#define PV_APITCH 40
#define PV_VPITCH 136
#define PV_ATILE (64 * PV_APITCH * 2)          // 5120
#define PV_VTILE (32 * PV_VPITCH * 2)          // 8704
#define PV_STAGE (4 * PV_ATILE + 2 * PV_VTILE) // 37888
#define PV_SMEM (2 * PV_STAGE)                 // 75776

__device__ __forceinline__ void pv_load_stage(uint32_t sb, int stage,
    const __nv_bfloat16* __restrict__ A0h, const __nv_bfloat16* __restrict__ A0l,
    const __nv_bfloat16* __restrict__ A1h, const __nv_bfloat16* __restrict__ A1l,
    const __nv_bfloat16* __restrict__ V0h, const __nv_bfloat16* __restrict__ V0l,
    const __nv_bfloat16* __restrict__ V1h, const __nv_bfloat16* __restrict__ V1l,
    int k0)
{
    const int tid = threadIdx.x;
    uint32_t base = sb + stage * PV_STAGE;
    {
        int r = tid >> 2, ch = tid & 3;
        uint32_t so = (uint32_t)(r * PV_APITCH * 2 + ch * 16);
        size_t go = (size_t)r * S + k0 + ch * 8;
        cp16(base + so,                A0h + go);
        cp16(base + PV_ATILE + so,     A0l + go);
        cp16(base + 2 * PV_ATILE + so, A1h + go);
        cp16(base + 3 * PV_ATILE + so, A1l + go);
    }
    uint32_t vbase = base + 4 * PV_ATILE;
#pragma unroll
    for (int i = 0; i < 2; i++) {
        int idx = tid + i * 256;
        int r = idx >> 4, ch = idx & 15;
        uint32_t so = (uint32_t)(r * PV_VPITCH * 2 + ch * 16);
        size_t go = (size_t)(k0 + r) * HD;
        if (ch < 8) {
            cp16ca(vbase + so,            V0h + go + ch * 8);
            cp16ca(vbase + PV_VTILE + so, V0l + go + ch * 8);
        } else {
            cp16ca(vbase + so,            V1h + go + (ch - 8) * 8);
            cp16ca(vbase + PV_VTILE + so, V1l + go + (ch - 8) * 8);
        }
    }
}

__global__ void __launch_bounds__(256, 2) pv_mma_kernel(
    const float* __restrict__ mix_b,
    const float* __restrict__ dyt_alpha, const float* __restrict__ dyt_w,
    const float* __restrict__ dyt_b, const float* __restrict__ depth_scale)
{
    extern __shared__ __align__(16) char smem[];
    uint32_t sb = smem_u32(smem);
    const int pair = blockIdx.z;
    const int b = pair >> 3, hp = pair & 7;
    const int h0 = hp * 2, h1 = h0 + 1;
    const int bh0 = b * 16 + h0, bh1 = bh0 + 1;
    const int Q0 = (gridDim.y - 1 - blockIdx.y) * 64;
    int Klim = Q0 + 128; if (Klim > S) Klim = S;
    const int cidx = Klim >> 6;
    const int nch = Klim >> 5;

    const __nv_bfloat16* A0h = g_mxh + (size_t)bh0 * S * S + (size_t)Q0 * S;
    const __nv_bfloat16* A0l = g_mxl + (size_t)bh0 * S * S + (size_t)Q0 * S;
    const __nv_bfloat16* A1h = g_mxh + (size_t)bh1 * S * S + (size_t)Q0 * S;
    const __nv_bfloat16* A1l = g_mxl + (size_t)bh1 * S * S + (size_t)Q0 * S;
    const __nv_bfloat16* V0h = g_vbh + (size_t)bh0 * S * HD;
    const __nv_bfloat16* V0l = g_vbl + (size_t)bh0 * S * HD;
    const __nv_bfloat16* V1h = g_vbh + (size_t)bh1 * S * HD;
    const __nv_bfloat16* V1l = g_vbl + (size_t)bh1 * S * HD;

    const int tid = threadIdx.x, lane = tid & 31, wid = tid >> 5;
    const int wm = wid & 3, wn = wid >> 2;
    const int a_r = lane & 15, a_c8 = (lane >> 4) * 8;
    const int bt_r = lane & 15, bt_c8 = (lane >> 4) * 8;

    float acc[8][4] = {};

    pv_load_stage(sb, 0, A0h, A0l, A1h, A1l, V0h, V0l, V1h, V1l, 0);
    asm volatile("cp.async.commit_group;" ::: "memory");

    for (int c = 0; c < nch; c++) {
        if (c + 1 < nch) {
            pv_load_stage(sb, (c + 1) & 1, A0h, A0l, A1h, A1l, V0h, V0l, V1h, V1l, (c + 1) * 32);
            asm volatile("cp.async.commit_group;" ::: "memory");
            asm volatile("cp.async.wait_group 1;" ::: "memory");
        } else {
            asm volatile("cp.async.wait_group 0;" ::: "memory");
        }
        __syncthreads();
        uint32_t base = sb + (c & 1) * PV_STAGE;
        uint32_t sAh = base + (wn * 2) * PV_ATILE;
        uint32_t sAl = base + (wn * 2 + 1) * PV_ATILE;
        uint32_t sVh = base + 4 * PV_ATILE;
        uint32_t sVl = sVh + PV_VTILE;
#pragma unroll
        for (int kk = 0; kk < 32; kk += 16) {
            uint32_t ah[4], al[4];
            uint32_t ro = (uint32_t)((wm * 16 + a_r) * PV_APITCH + kk + a_c8) * 2;
            ldsm_x4(ah, sAh + ro);
            ldsm_x4(al, sAl + ro);
            uint32_t bhf[4][4], blf[4][4];
#pragma unroll
            for (int t = 0; t < 4; t++) {
                uint32_t vo = (uint32_t)((kk + bt_r) * PV_VPITCH + wn * 64 + t * 16 + bt_c8) * 2;
                ldsm_x4_t(bhf[t], sVh + vo);
                ldsm_x4_t(blf[t], sVl + vo);
            }
#pragma unroll
            for (int nt = 0; nt < 8; nt++) {
                const uint32_t* bp  = &bhf[nt >> 1][(nt & 1) * 2];
                const uint32_t* blp = &blf[nt >> 1][(nt & 1) * 2];
                mma_bf16(acc[nt], ah, bp);
                mma_bf16(acc[nt], al, bp);
                mma_bf16(acc[nt], ah, blp);
            }
        }
        __syncthreads();
    }

    const int bhh = wn ? bh1 : bh0;
    const float* suff = g_suffV + ((size_t)bhh * 17 + cidx) * HD;
    const float* csum = g_suffV + ((size_t)bhh * 17 + 0) * HD;
    const float* rcm = g_rowconst + bhh * S;
    const float mb = mix_b[wn ? h1 : h0];
    const float alpha = dyt_alpha[0], ds = depth_scale[0];
    const int q0r = Q0 + wm * 16 + (lane >> 2);
    const float cm0 = rcm[q0r];
    const float cm1 = rcm[q0r + 8];
    __nv_bfloat16* Oh = g_aoh + (size_t)b * S * E + h0 * HD;
    __nv_bfloat16* Ol = g_aol + (size_t)b * S * E + h0 * HD;

#pragma unroll
    for (int nt = 0; nt < 8; nt++) {
        int d = wn * 64 + nt * 8 + (lane & 3) * 2;
        int dl = d & 63;
        float sw0 = suff[dl], sw1 = suff[dl + 1];
        float cs0 = csum[dl], cs1 = csum[dl + 1];
        float w0 = dyt_w[dl], w1 = dyt_w[dl + 1];
        float bb0 = dyt_b[dl], bb1 = dyt_b[dl + 1];
#pragma unroll
        for (int half = 0; half < 2; half++) {
            int q = q0r + half * 8;
            float cm = half ? cm1 : cm0;
            float v0 = acc[nt][half * 2 + 0] + cm * sw0 + mb * cs0;
            float v1 = acc[nt][half * 2 + 1] + cm * sw1 + mb * cs1;
            v0 = (tanhf(alpha * v0) * w0 + bb0) * ds;
            v1 = (tanhf(alpha * v1) * w1 + bb1) * ds;
            __nv_bfloat16 h0v = __float2bfloat16(v0), h1v = __float2bfloat16(v1);
            *(__nv_bfloat162*)&Oh[(size_t)q * E + d] = __halves2bfloat162(h0v, h1v);
            *(__nv_bfloat162*)&Ol[(size_t)q * E + d] = __halves2bfloat162(
                __float2bfloat16(v0 - __bfloat162float(h0v)),
                __float2bfloat16(v1 - __bfloat162float(h1v)));
        }
    }
}

// ============================================================================
// Launch  (champion configuration)
// ============================================================================
extern "C" void kernel_launch(void* const* d_in, const int* in_sizes, int n_in,
                              void* d_out, int out_size)
{
    const float* Q   = (const float*)d_in[0];
    const float* K   = (const float*)d_in[1];
    const float* V   = (const float*)d_in[2];
    const float* Wq  = (const float*)d_in[3];
    const float* bq  = (const float*)d_in[4];
    const float* Wk  = (const float*)d_in[5];
    const float* bk  = (const float*)d_in[6];
    const float* Wv  = (const float*)d_in[7];
    const float* bv  = (const float*)d_in[8];
    const float* Wo  = (const float*)d_in[9];
    const float* bo  = (const float*)d_in[10];
    const float* kq_w = (const float*)d_in[11];
    const float* kq_b = (const float*)d_in[12];
    const float* mix_w = (const float*)d_in[13];
    const float* mix_b = (const float*)d_in[14];
    const float* dyt_alpha = (const float*)d_in[15];
    const float* dyt_w = (const float*)d_in[16];
    const float* dyt_b = (const float*)d_in[17];
    const float* depth_scale = (const float*)d_in[18];

    cudaFuncSetAttribute(gemm_qkv_tc, cudaFuncAttributeMaxDynamicSharedMemorySize, GEMM_SMEM);
    cudaFuncSetAttribute(gemm_out_tc, cudaFuncAttributeMaxDynamicSharedMemorySize, GEMM_SMEM);
    cudaFuncSetAttribute(logits_mma_kernel, cudaFuncAttributeMaxDynamicSharedMemorySize, LOG_SMEM);
    cudaFuncSetAttribute(pv_mma_kernel, cudaFuncAttributeMaxDynamicSharedMemorySize, PV_SMEM);

    asplit_kernel<<<dim3(2048, 1, 3), 256>>>(Q, K, V);
    wsplit_kernel<<<dim3(32, 32, 4), dim3(32, 8)>>>(Wq, Wk, Wv, Wo);
    gemm_qkv_tc<<<dim3(8, 16, 3), 256, GEMM_SMEM>>>(bq, bk, bv);
    vchunk_kernel<<<dim3(BH, 16), 256>>>();
    vscan_kernel<<<BH, 64>>>();
    logits_mma_kernel<<<dim3(36, BH), 256, LOG_SMEM>>>();
    conv_softmax_kernel<<<dim3(S / QROWS, BH / 2), 256>>>(kq_w, kq_b, mix_w);
    pv_mma_kernel<<<dim3(1, S / 64, BH / 2), 256, PV_SMEM>>>(mix_b, dyt_alpha, dyt_w, dyt_b, depth_scale);
    gemm_out_tc<<<dim3(8, 16), 256, GEMM_SMEM>>>(bo, (float*)d_out);
}